// round 6
// baseline (speedup 1.0000x reference)
#include <cuda_runtime.h>
#include <cuda_bf16.h>
#include <math.h>
#include <stdint.h>

// ---------------- problem constants ----------------
#define D_     384
#define H_     6
#define HD_    64
#define L_     4
#define B_     8
#define N_     1024
#define SEQ_   1025
#define ROWS_  (B_*SEQ_)     // 8200
#define ROWSP_ 8320          // padded to 65*128 -> no M predicates in GEMM
#define NC_    2
#define QKV_N  (3*D_)        // 1152
#define FF_    (4*D_)        // 1536

typedef unsigned long long u64;
typedef unsigned int u32;

#define PACKF2(dst, lo, hi) asm("mov.b64 %0, {%1, %2};" : "=l"(dst) : "f"(lo), "f"(hi))
#define UNPACKF2(lo, hi, src) asm("mov.b64 {%0, %1}, %2;" : "=f"(lo), "=f"(hi) : "l"(src))
#define FMAF2(acc, a, b) asm("fma.rn.f32x2 %0, %1, %2, %0;" : "+l"(acc) : "l"(a), "l"(b))

__device__ __forceinline__ float f2tf32(float f) {
    u32 u; asm("cvt.rna.tf32.f32 %0, %1;" : "=r"(u) : "f"(f));
    return __uint_as_float(u);
}

#define MMA_TF32(c, a, b) \
    asm("mma.sync.aligned.m16n8k8.row.col.f32.tf32.tf32.f32 " \
        "{%0,%1,%2,%3}, {%4,%5,%6,%7}, {%8,%9}, {%0,%1,%2,%3};" \
        : "+f"(c[0]), "+f"(c[1]), "+f"(c[2]), "+f"(c[3]) \
        : "r"(a[0]), "r"(a[1]), "r"(a[2]), "r"(a[3]), "r"(b[0]), "r"(b[1]))

#define CP16(saddr, gptr) \
    asm volatile("cp.async.ca.shared.global [%0], [%1], 16;" :: "r"(saddr), "l"(gptr))
#define CP_COMMIT() asm volatile("cp.async.commit_group;" ::: "memory")
#define CP_WAIT0()  asm volatile("cp.async.wait_group 0;" ::: "memory")

__device__ __forceinline__ u32 smem_u32(const void* p) {
    u32 a;
    asm("{ .reg .u64 t; cvta.to.shared.u64 t, %1; cvt.u32.u64 %0, t; }" : "=r"(a) : "l"(p));
    return a;
}

// ---------------- scratch (device globals; no allocation allowed) ----------
__device__ float g_x[ROWSP_*D_];        // residual (fp32)
__device__ float g_h[ROWSP_*D_];        // ln out (tf32-rounded); pad rows stay 0
__device__ float g_qkv[ROWSP_*QKV_N];   // qkv (fp32); also patch-embed tmp
__device__ float g_attn[ROWSP_*D_];     // attn out (tf32-rounded); pad rows stay 0
__device__ float g_mlp[ROWSP_*FF_];     // gelu out (tf32-rounded)
__device__ float g_pw[L_*D_*QKV_N];
__device__ float g_pb[L_*QKV_N];
__device__ float g_qkvT[L_*QKV_N*D_];   // [l][n][k] tf32-rounded
__device__ float g_woT[L_*D_*D_];
__device__ float g_w1T[L_*FF_*D_];
__device__ float g_w2T[L_*D_*FF_];
__device__ float g_patT[D_*256];
__device__ float g_img[B_*N_*256];      // images tf32-rounded
__device__ float g_lg[B_*N_*NC_];

// ---------------- GEMM v4 (tf32 mma, 64x64 warp tiles, cp.async) -------------
#define EPI_BIAS 0
#define EPI_RES  1
#define EPI_GELU 2
#define SSTRIDE 36
#define SBUF    (128*SSTRIDE)

__device__ __forceinline__ float gelu_f(float v) {
    return 0.5f * v * (1.f + erff(v * 0.70710678118654752f));
}

template<int EPI>
__global__ __launch_bounds__(128, 2)
void gemm4_k(const float* __restrict__ A, const float* __restrict__ Bm,
             const float* __restrict__ bias, const float* __restrict__ res,
             float* __restrict__ C, int M, int N, int K)
{
    extern __shared__ float sm[];
    const int tid  = threadIdx.x;
    const int lane = tid & 31, wid = tid >> 5;
    const int wm = (wid >> 1) * 64, wn = (wid & 1) * 64;
    const int g = lane >> 2, t = lane & 3;
    const size_t row0 = (size_t)blockIdx.y * 128;
    const size_t col0 = (size_t)blockIdx.x * 128;

    const int lr = tid >> 3;
    const int lk = (tid & 7) * 4;

    const float* Aptr = A + (row0 + lr) * K + lk;
    const float* Bptr = Bm + (col0 + lr) * K + lk;
    const u32 asb0 = smem_u32(sm);
    const u32 dst_off = (u32)(lr * SSTRIDE + lk) * 4;

    float c[4][8][4];
    #pragma unroll
    for (int i = 0; i < 4; i++)
        #pragma unroll
        for (int j = 0; j < 8; j++)
            #pragma unroll
            for (int f = 0; f < 4; f++) c[i][j][f] = 0.f;

    const int KT = K >> 5;

    {
        u32 ad = asb0 + dst_off;
        u32 bd = asb0 + 2*SBUF*4 + dst_off;
        #pragma unroll
        for (int it = 0; it < 8; it++) {
            CP16(ad + it*16*SSTRIDE*4, Aptr + (size_t)it*16*K);
            CP16(bd + it*16*SSTRIDE*4, Bptr + (size_t)it*16*K);
        }
        CP_COMMIT();
    }

    int buf = 0;
    for (int kt = 0; kt < KT; kt++) {
        CP_WAIT0();
        __syncthreads();
        if (kt + 1 < KT) {
            int k0 = (kt + 1) << 5;
            u32 ad = asb0 + (buf^1)*SBUF*4 + dst_off;
            u32 bd = asb0 + (2 + (buf^1))*SBUF*4 + dst_off;
            #pragma unroll
            for (int it = 0; it < 8; it++) {
                CP16(ad + it*16*SSTRIDE*4, Aptr + k0 + (size_t)it*16*K);
                CP16(bd + it*16*SSTRIDE*4, Bptr + k0 + (size_t)it*16*K);
            }
            CP_COMMIT();
        }
        const float* As_ = sm + buf*SBUF;
        const float* Bs_ = sm + (2 + buf)*SBUF;
        #pragma unroll
        for (int ks = 0; ks < 4; ks++) {
            const int k8 = ks * 8;
            u32 a[4][4], b[8][2];
            #pragma unroll
            for (int i = 0; i < 4; i++) {
                int m0 = wm + 16*i;
                a[i][0] = __float_as_uint(As_[(m0+g  )*SSTRIDE + k8 + t  ]);
                a[i][1] = __float_as_uint(As_[(m0+g+8)*SSTRIDE + k8 + t  ]);
                a[i][2] = __float_as_uint(As_[(m0+g  )*SSTRIDE + k8 + t+4]);
                a[i][3] = __float_as_uint(As_[(m0+g+8)*SSTRIDE + k8 + t+4]);
            }
            #pragma unroll
            for (int j = 0; j < 8; j++) {
                int n0 = wn + 8*j;
                b[j][0] = __float_as_uint(Bs_[(n0+g)*SSTRIDE + k8 + t  ]);
                b[j][1] = __float_as_uint(Bs_[(n0+g)*SSTRIDE + k8 + t+4]);
            }
            #pragma unroll
            for (int i = 0; i < 4; i++)
                #pragma unroll
                for (int j = 0; j < 8; j++)
                    MMA_TF32(c[i][j], a[i], b[j]);
        }
        __syncthreads();
        buf ^= 1;
    }

    #pragma unroll
    for (int i = 0; i < 4; i++) {
        size_t r0 = row0 + wm + 16*i + g;
        size_t r1 = r0 + 8;
        #pragma unroll
        for (int j = 0; j < 8; j++) {
            int cb = (int)col0 + wn + 8*j + 2*t;
            float b0 = bias[cb], b1 = bias[cb+1];
            float v0 = c[i][j][0] + b0, v1 = c[i][j][1] + b1;
            float v2 = c[i][j][2] + b0, v3 = c[i][j][3] + b1;
            if (EPI == EPI_RES) {
                float2 ra = *(const float2*)&res[r0*N + cb];
                float2 rb = *(const float2*)&res[r1*N + cb];
                v0 += ra.x; v1 += ra.y; v2 += rb.x; v3 += rb.y;
            }
            if (EPI == EPI_GELU) {
                v0 = f2tf32(gelu_f(v0)); v1 = f2tf32(gelu_f(v1));
                v2 = f2tf32(gelu_f(v2)); v3 = f2tf32(gelu_f(v3));
            }
            *(float2*)&C[r0*N + cb] = make_float2(v0, v1);
            *(float2*)&C[r1*N + cb] = make_float2(v2, v3);
        }
    }
}

// ---------------- layernorm: emits tf32-rounded fp32 -------------------------
__global__ void ln_k(const float* __restrict__ x, const float* __restrict__ g,
                     const float* __restrict__ b, float* __restrict__ y)
{
    int row = blockIdx.x;
    int tid = threadIdx.x;
    const float* xr = x + (size_t)row*D_;
    float v[3];
    float s = 0.f;
    #pragma unroll
    for (int i = 0; i < 3; i++) { v[i] = xr[tid + 128*i]; s += v[i]; }
    __shared__ float red[128];
    red[tid] = s; __syncthreads();
    for (int o = 64; o > 0; o >>= 1) { if (tid < o) red[tid] += red[tid+o]; __syncthreads(); }
    float mu = red[0] * (1.f/D_);
    __syncthreads();
    float s2 = 0.f;
    #pragma unroll
    for (int i = 0; i < 3; i++) { float d = v[i]-mu; s2 += d*d; }
    red[tid] = s2; __syncthreads();
    for (int o = 64; o > 0; o >>= 1) { if (tid < o) red[tid] += red[tid+o]; __syncthreads(); }
    float inv = rsqrtf(red[0]*(1.f/D_) + 1e-5f);
    float* yr = y + (size_t)row*D_;
    #pragma unroll
    for (int i = 0; i < 3; i++) {
        int c = tid + 128*i;
        yr[c] = f2tf32((v[i]-mu)*inv*g[c] + b[c]);
    }
}

// ---------------- attention v4: conflict-free smem (stride 65, scalar) -------
__global__ __launch_bounds__(256, 2)
void attn4_k(const float* __restrict__ qkv, float* __restrict__ out)
{
    __shared__ float ss[8][1056];      // scores; 1025..1055 zeroed
    __shared__ float Ks[32][65];       // K/V tile, stride 65: conflict-free scalar
    const int tid  = threadIdx.x;
    const int w    = tid >> 5;         // warp = local query
    const int lane = tid & 31;
    const int bh = blockIdx.y;
    const int b = bh / H_, h = bh % H_;
    const int qg = blockIdx.x * 8 + w;
    const float* base = qkv + (size_t)b*SEQ_*QKV_N;

    // query row in 64 scalar registers
    float qv[64];
    {
        int qc = (qg < SEQ_) ? qg : (SEQ_-1);
        const float4* qr = (const float4*)&base[(size_t)qc*QKV_N + h*HD_];
        #pragma unroll
        for (int e4 = 0; e4 < 16; e4++) {
            float4 t = qr[e4];
            qv[e4*4+0] = t.x; qv[e4*4+1] = t.y; qv[e4*4+2] = t.z; qv[e4*4+3] = t.w;
        }
    }

    const int jr = tid >> 3;           // tile row 0..31
    const int e0 = (tid & 7) * 8;      // col chunk

    // ---- phase 1: scores ----
    for (int kb = 0; kb < SEQ_; kb += 32) {
        __syncthreads();
        int j = kb + jr;
        if (j < SEQ_) {
            const float4* kr = (const float4*)&base[(size_t)j*QKV_N + D_ + h*HD_ + e0];
            float4 v0 = kr[0], v1 = kr[1];
            Ks[jr][e0+0] = v0.x; Ks[jr][e0+1] = v0.y; Ks[jr][e0+2] = v0.z; Ks[jr][e0+3] = v0.w;
            Ks[jr][e0+4] = v1.x; Ks[jr][e0+5] = v1.y; Ks[jr][e0+6] = v1.z; Ks[jr][e0+7] = v1.w;
        } else {
            #pragma unroll
            for (int i = 0; i < 8; i++) Ks[jr][e0+i] = 0.f;
        }
        __syncthreads();
        int jj = kb + lane;
        float d = 0.f;
        #pragma unroll
        for (int e = 0; e < 64; e++) d += qv[e] * Ks[lane][e];   // bank (lane+e)%32: conflict-free
        if (jj < SEQ_) ss[w][jj] = d * 0.125f;
    }

    // ---- phase 2: softmax (per-warp row) ----
    float mx = -1e30f;
    for (int j = lane; j < SEQ_; j += 32) mx = fmaxf(mx, ss[w][j]);
    #pragma unroll
    for (int o = 16; o > 0; o >>= 1) mx = fmaxf(mx, __shfl_xor_sync(0xffffffffu, mx, o));
    float sum = 0.f;
    for (int j = lane; j < SEQ_; j += 32) {
        float e = __expf(ss[w][j] - mx);
        ss[w][j] = e;
        sum += e;
    }
    #pragma unroll
    for (int o = 16; o > 0; o >>= 1) sum += __shfl_xor_sync(0xffffffffu, sum, o);
    float inv = 1.f / sum;
    if (lane > 0) ss[w][1024 + lane] = 0.f;   // pad 1025..1055
    __syncwarp();

    // ---- phase 3: attn @ V (lane owns dims lane, lane+32) ----
    float o0 = 0.f, o1 = 0.f;
    for (int kb = 0; kb < SEQ_; kb += 32) {
        __syncthreads();
        int j = kb + jr;
        if (j < SEQ_) {
            const float4* vr = (const float4*)&base[(size_t)j*QKV_N + 2*D_ + h*HD_ + e0];
            float4 v0 = vr[0], v1 = vr[1];
            Ks[jr][e0+0] = v0.x; Ks[jr][e0+1] = v0.y; Ks[jr][e0+2] = v0.z; Ks[jr][e0+3] = v0.w;
            Ks[jr][e0+4] = v1.x; Ks[jr][e0+5] = v1.y; Ks[jr][e0+6] = v1.z; Ks[jr][e0+7] = v1.w;
        } else {
            #pragma unroll
            for (int i = 0; i < 8; i++) Ks[jr][e0+i] = 0.f;
        }
        __syncthreads();
        #pragma unroll
        for (int jj = 0; jj < 32; jj++) {
            float p = ss[w][kb + jj];          // broadcast
            o0 += p * Ks[jj][lane];            // bank (jj*65+lane)%32: conflict-free
            o1 += p * Ks[jj][lane + 32];
        }
    }

    if (qg < SEQ_) {
        float* orow = &out[((size_t)b*SEQ_ + qg)*D_ + h*HD_];
        orow[lane]      = f2tf32(o0 * inv);
        orow[lane + 32] = f2tf32(o1 * inv);
    }
}

// ---------------- patch-embed assemble ---------------------------------------
__global__ void assemble_k(const float* __restrict__ tmp, const float* __restrict__ cls,
                           float* __restrict__ x)
{
    int idx = blockIdx.x*blockDim.x + threadIdx.x;
    if (idx >= ROWS_*D_) return;
    int d = idx % D_;
    int rp = idx / D_;
    int pos = rp % SEQ_;
    int b = rp / SEQ_;
    float val = (pos == 0) ? cls[d] : tmp[((size_t)b*N_ + pos-1)*D_ + d];
    float expo = (float)(d & ~1) * (1.f/(float)D_);
    float ang = (float)pos / powf(10000.f, expo);
    float pe = (d & 1) ? cosf(ang) : sinf(ang);
    x[idx] = val + pe;
}

// ---------------- repack per-layer QKV weights -------------------------------
__global__ void repack_k(const float* __restrict__ wq, const float* __restrict__ wk,
                         const float* __restrict__ wv, const float* __restrict__ bq,
                         const float* __restrict__ bk, const float* __restrict__ bv,
                         float* __restrict__ pw, float* __restrict__ pb)
{
    int idx = blockIdx.x*blockDim.x + threadIdx.x;
    if (idx >= L_*D_*QKV_N) return;
    int j = idx % QKV_N;
    int t = idx / QKV_N;
    int k = t % D_;
    int l = t / D_;
    int sec = j / D_, jj = j % D_, h = jj >> 6, e = jj & 63;
    const float* w = (sec == 0) ? wq : (sec == 1) ? wk : wv;
    pw[idx] = w[(((size_t)l*H_ + h)*D_ + k)*HD_ + e];
    if (k == 0) {
        const float* bb = (sec == 0) ? bq : (sec == 1) ? bk : bv;
        pb[l*QKV_N + j] = bb[((size_t)l*H_ + h)*HD_ + e];
    }
}

// ---------------- transpose + tf32 round -------------------------------------
__global__ void trT_k(const float* __restrict__ src, float* __restrict__ dst,
                      int K, int N, int total)
{
    int idx = blockIdx.x*blockDim.x + threadIdx.x;
    if (idx >= total) return;
    int nk = N*K;
    int m = idx / nk;
    int t = idx % nk;
    int n = t / K, k = t % K;
    dst[idx] = f2tf32(src[((size_t)m*K + k)*N + n]);
}

// ---------------- plain tf32 round -------------------------------------------
__global__ void rnd_k(const float* __restrict__ src, float* __restrict__ dst, int total)
{
    int idx = blockIdx.x*blockDim.x + threadIdx.x;
    if (idx >= total) return;
    dst[idx] = f2tf32(src[idx]);
}

// ---------------- classifier logits (NC=2) -----------------------------------
__global__ void logits_k(const float* __restrict__ x, const float* __restrict__ cw,
                         const float* __restrict__ cb, float* __restrict__ lg)
{
    int idx = blockIdx.x*blockDim.x + threadIdx.x;
    if (idx >= B_*N_*NC_) return;
    int c = idx & 1;
    int bn = idx >> 1;
    int n = bn % N_, b = bn / N_;
    const float4* xr = (const float4*)(x + ((size_t)b*SEQ_ + n + 1)*D_);
    float s = cb[c];
    #pragma unroll 4
    for (int d4 = 0; d4 < D_/4; d4++) {
        float4 xv = xr[d4];
        s += xv.x*cw[(d4*4+0)*NC_ + c] + xv.y*cw[(d4*4+1)*NC_ + c]
           + xv.z*cw[(d4*4+2)*NC_ + c] + xv.w*cw[(d4*4+3)*NC_ + c];
    }
    lg[idx] = s;
}

// ---------------- deconv upsample ---------------------------------------------
__global__ void up_k(const float* __restrict__ lg, const float* __restrict__ dw,
                     const float* __restrict__ db, float* __restrict__ out)
{
    int idx = blockIdx.x*blockDim.x + threadIdx.x;
    if (idx >= B_*NC_*N_*16*16) return;
    int ww = idx & 15;
    int t = idx >> 4;
    int hh = t & 15; t >>= 4;
    int n = t % N_;  t /= N_;
    int o = t & 1;   int b = t >> 1;
    float s = db[o];
    #pragma unroll
    for (int c = 0; c < NC_; c++)
        s += lg[((size_t)b*N_ + n)*NC_ + c] * dw[((c*NC_ + o)*16 + hh)*16 + ww];
    out[idx] = s;
}

// ---------------- launch ------------------------------------------------------
extern "C" void kernel_launch(void* const* d_in, const int* in_sizes, int n_in,
                              void* d_out, int out_size)
{
    const float* images  = (const float*)d_in[0];
    const float* patch_w = (const float*)d_in[2];
    const float* patch_b = (const float*)d_in[3];
    const float* cls_tok = (const float*)d_in[4];
    const float* ln1_g   = (const float*)d_in[5];
    const float* ln1_b   = (const float*)d_in[6];
    const float* wq      = (const float*)d_in[7];
    const float* bq      = (const float*)d_in[8];
    const float* wk      = (const float*)d_in[9];
    const float* bk      = (const float*)d_in[10];
    const float* wv      = (const float*)d_in[11];
    const float* bv      = (const float*)d_in[12];
    const float* wo      = (const float*)d_in[13];
    const float* bo      = (const float*)d_in[14];
    const float* ln2_g   = (const float*)d_in[15];
    const float* ln2_b   = (const float*)d_in[16];
    const float* w1      = (const float*)d_in[17];
    const float* b1      = (const float*)d_in[18];
    const float* w2      = (const float*)d_in[19];
    const float* b2      = (const float*)d_in[20];
    const float* cls_w   = (const float*)d_in[21];
    const float* cls_b   = (const float*)d_in[22];
    const float* dc_w    = (const float*)d_in[23];
    const float* dc_b    = (const float*)d_in[24];
    float* out = (float*)d_out;

    float *x, *h, *qkv, *attn, *mlp, *pw, *pb, *lg;
    float *qkvT, *woT, *w1T, *w2T, *patT, *img;
    cudaGetSymbolAddress((void**)&x,    g_x);
    cudaGetSymbolAddress((void**)&h,    g_h);
    cudaGetSymbolAddress((void**)&qkv,  g_qkv);
    cudaGetSymbolAddress((void**)&attn, g_attn);
    cudaGetSymbolAddress((void**)&mlp,  g_mlp);
    cudaGetSymbolAddress((void**)&pw,   g_pw);
    cudaGetSymbolAddress((void**)&pb,   g_pb);
    cudaGetSymbolAddress((void**)&qkvT, g_qkvT);
    cudaGetSymbolAddress((void**)&woT,  g_woT);
    cudaGetSymbolAddress((void**)&w1T,  g_w1T);
    cudaGetSymbolAddress((void**)&w2T,  g_w2T);
    cudaGetSymbolAddress((void**)&patT, g_patT);
    cudaGetSymbolAddress((void**)&img,  g_img);
    cudaGetSymbolAddress((void**)&lg,   g_lg);

    const int SMEM_SZ = 4*SBUF*4;   // 73728 B
    cudaFuncSetAttribute(gemm4_k<EPI_BIAS>, cudaFuncAttributeMaxDynamicSharedMemorySize, SMEM_SZ);
    cudaFuncSetAttribute(gemm4_k<EPI_RES>,  cudaFuncAttributeMaxDynamicSharedMemorySize, SMEM_SZ);
    cudaFuncSetAttribute(gemm4_k<EPI_GELU>, cudaFuncAttributeMaxDynamicSharedMemorySize, SMEM_SZ);

    // ---- weight prep ----
    repack_k<<<(L_*D_*QKV_N + 255)/256, 256>>>(wq, wk, wv, bq, bk, bv, pw, pb);
    trT_k<<<(L_*QKV_N*D_ + 255)/256, 256>>>(pw,      qkvT, D_,  QKV_N, L_*QKV_N*D_);
    trT_k<<<(L_*D_*D_    + 255)/256, 256>>>(wo,      woT,  D_,  D_,    L_*D_*D_);
    trT_k<<<(L_*FF_*D_   + 255)/256, 256>>>(w1,      w1T,  D_,  FF_,   L_*FF_*D_);
    trT_k<<<(L_*D_*FF_   + 255)/256, 256>>>(w2,      w2T,  FF_, D_,    L_*D_*FF_);
    trT_k<<<(D_*256      + 255)/256, 256>>>(patch_w, patT, 256, D_,    D_*256);
    rnd_k<<<(B_*N_*256   + 255)/256, 256>>>(images,  img,  B_*N_*256);

    // ---- patch embed GEMM ----
    {
        dim3 g(D_/128, (B_*N_)/128);
        gemm4_k<EPI_BIAS><<<g, 128, SMEM_SZ>>>(img, patT, patch_b, nullptr, qkv,
                                               B_*N_, D_, 256);
    }
    assemble_k<<<(ROWS_*D_ + 255)/256, 256>>>(qkv, cls_tok, x);

    dim3 gq(QKV_N/128, ROWSP_/128);
    dim3 go(D_/128,    ROWSP_/128);
    dim3 g1(FF_/128,   ROWSP_/128);
    dim3 ga((SEQ_+7)/8, B_*H_);

    for (int l = 0; l < L_; l++) {
        ln_k<<<ROWS_, 128>>>(x, ln1_g + l*D_, ln1_b + l*D_, h);
        gemm4_k<EPI_BIAS><<<gq, 128, SMEM_SZ>>>(h, qkvT + (size_t)l*QKV_N*D_,
                                                pb + l*QKV_N, nullptr,
                                                qkv, ROWSP_, QKV_N, D_);
        attn4_k<<<ga, 256>>>(qkv, attn);
        gemm4_k<EPI_RES><<<go, 128, SMEM_SZ>>>(attn, woT + (size_t)l*D_*D_,
                                               bo + l*D_, x,
                                               x, ROWSP_, D_, D_);
        ln_k<<<ROWS_, 128>>>(x, ln2_g + l*D_, ln2_b + l*D_, h);
        gemm4_k<EPI_GELU><<<g1, 128, SMEM_SZ>>>(h, w1T + (size_t)l*FF_*D_,
                                                b1 + l*FF_, nullptr,
                                                mlp, ROWSP_, FF_, D_);
        gemm4_k<EPI_RES><<<go, 128, SMEM_SZ>>>(mlp, w2T + (size_t)l*D_*FF_,
                                               b2 + l*D_, x,
                                               x, ROWSP_, D_, FF_);
    }

    logits_k<<<(B_*N_*NC_ + 127)/128, 128>>>(x, cls_w, cls_b, lg);
    up_k<<<(B_*NC_*N_*256 + 255)/256, 256>>>(lg, dc_w, dc_b, out);
    (void)in_sizes; (void)n_in; (void)out_size;
}

// round 7
// speedup vs baseline: 2.7144x; 2.7144x over previous
#include <cuda_runtime.h>
#include <cuda_bf16.h>
#include <math.h>
#include <stdint.h>

// ---------------- problem constants ----------------
#define D_     384
#define H_     6
#define HD_    64
#define L_     4
#define B_     8
#define N_     1024
#define SEQ_   1025
#define ROWS_  (B_*SEQ_)     // 8200
#define ROWSP_ 8320          // padded: no M predicates in weight GEMMs
#define NC_    2
#define QKV_N  (3*D_)        // 1152
#define FF_    (4*D_)        // 1536
#define SP_    1152          // padded seq (9*128) for attention GEMMs
#define KP_    1056          // padded key-K for P@V (33*32)

typedef unsigned long long u64;
typedef unsigned int u32;

__device__ __forceinline__ float f2tf32(float f) {
    u32 u; asm("cvt.rna.tf32.f32 %0, %1;" : "=r"(u) : "f"(f));
    return __uint_as_float(u);
}

#define MMA_TF32(c, a, b) \
    asm("mma.sync.aligned.m16n8k8.row.col.f32.tf32.tf32.f32 " \
        "{%0,%1,%2,%3}, {%4,%5,%6,%7}, {%8,%9}, {%0,%1,%2,%3};" \
        : "+f"(c[0]), "+f"(c[1]), "+f"(c[2]), "+f"(c[3]) \
        : "r"(a[0]), "r"(a[1]), "r"(a[2]), "r"(a[3]), "r"(b[0]), "r"(b[1]))

#define CP16(saddr, gptr) \
    asm volatile("cp.async.ca.shared.global [%0], [%1], 16;" :: "r"(saddr), "l"(gptr))
#define CP_COMMIT() asm volatile("cp.async.commit_group;" ::: "memory")
#define CP_WAIT0()  asm volatile("cp.async.wait_group 0;" ::: "memory")

__device__ __forceinline__ u32 smem_u32(const void* p) {
    u32 a;
    asm("{ .reg .u64 t; cvta.to.shared.u64 t, %1; cvt.u32.u64 %0, t; }" : "=r"(a) : "l"(p));
    return a;
}

// ---------------- scratch (device globals; no allocation allowed) ----------
__device__ float g_x[ROWSP_*D_];
__device__ float g_h[ROWSP_*D_];
__device__ float g_qkv[ROWSP_*QKV_N];
__device__ float g_attn[ROWSP_*D_];
__device__ float g_mlp[ROWSP_*FF_];
__device__ float g_pb[L_*QKV_N];
__device__ float g_qkvT[L_*QKV_N*D_];
__device__ float g_woT[L_*D_*D_];
__device__ float g_w1T[L_*FF_*D_];
__device__ float g_w2T[L_*D_*FF_];
__device__ float g_patT[D_*256];
__device__ float g_img[B_*N_*256];
__device__ float g_lg[B_*N_*NC_];
__device__ float g_s[48*SP_*SP_];     // attention scores / probs (255 MB)
__device__ float g_vT[48*HD_*KP_];    // V transposed per (b,h)

// ---------------- GEMM v4 (tf32 mma, 64x64 warp tiles, cp.async) -------------
#define EPI_BIAS 0
#define EPI_RES  1
#define EPI_GELU 2
#define SSTRIDE 36
#define SBUF    (128*SSTRIDE)

__device__ __forceinline__ float gelu_f(float v) {
    return 0.5f * v * (1.f + erff(v * 0.70710678118654752f));
}

template<int EPI>
__global__ __launch_bounds__(128, 2)
void gemm4_k(const float* __restrict__ A, const float* __restrict__ Bm,
             const float* __restrict__ bias, const float* __restrict__ res,
             float* __restrict__ C, int M, int N, int K)
{
    extern __shared__ float sm[];
    const int tid  = threadIdx.x;
    const int lane = tid & 31, wid = tid >> 5;
    const int wm = (wid >> 1) * 64, wn = (wid & 1) * 64;
    const int g = lane >> 2, t = lane & 3;
    const size_t row0 = (size_t)blockIdx.y * 128;
    const size_t col0 = (size_t)blockIdx.x * 128;

    const int lr = tid >> 3;
    const int lk = (tid & 7) * 4;

    const float* Aptr = A + (row0 + lr) * K + lk;
    const float* Bptr = Bm + (col0 + lr) * K + lk;
    const u32 asb0 = smem_u32(sm);
    const u32 dst_off = (u32)(lr * SSTRIDE + lk) * 4;

    float c[4][8][4];
    #pragma unroll
    for (int i = 0; i < 4; i++)
        #pragma unroll
        for (int j = 0; j < 8; j++)
            #pragma unroll
            for (int f = 0; f < 4; f++) c[i][j][f] = 0.f;

    const int KT = K >> 5;

    {
        u32 ad = asb0 + dst_off;
        u32 bd = asb0 + 2*SBUF*4 + dst_off;
        #pragma unroll
        for (int it = 0; it < 8; it++) {
            CP16(ad + it*16*SSTRIDE*4, Aptr + (size_t)it*16*K);
            CP16(bd + it*16*SSTRIDE*4, Bptr + (size_t)it*16*K);
        }
        CP_COMMIT();
    }

    int buf = 0;
    for (int kt = 0; kt < KT; kt++) {
        CP_WAIT0();
        __syncthreads();
        if (kt + 1 < KT) {
            int k0 = (kt + 1) << 5;
            u32 ad = asb0 + (buf^1)*SBUF*4 + dst_off;
            u32 bd = asb0 + (2 + (buf^1))*SBUF*4 + dst_off;
            #pragma unroll
            for (int it = 0; it < 8; it++) {
                CP16(ad + it*16*SSTRIDE*4, Aptr + k0 + (size_t)it*16*K);
                CP16(bd + it*16*SSTRIDE*4, Bptr + k0 + (size_t)it*16*K);
            }
            CP_COMMIT();
        }
        const float* As_ = sm + buf*SBUF;
        const float* Bs_ = sm + (2 + buf)*SBUF;
        #pragma unroll
        for (int ks = 0; ks < 4; ks++) {
            const int k8 = ks * 8;
            u32 a[4][4], b[8][2];
            #pragma unroll
            for (int i = 0; i < 4; i++) {
                int m0 = wm + 16*i;
                a[i][0] = __float_as_uint(As_[(m0+g  )*SSTRIDE + k8 + t  ]);
                a[i][1] = __float_as_uint(As_[(m0+g+8)*SSTRIDE + k8 + t  ]);
                a[i][2] = __float_as_uint(As_[(m0+g  )*SSTRIDE + k8 + t+4]);
                a[i][3] = __float_as_uint(As_[(m0+g+8)*SSTRIDE + k8 + t+4]);
            }
            #pragma unroll
            for (int j = 0; j < 8; j++) {
                int n0 = wn + 8*j;
                b[j][0] = __float_as_uint(Bs_[(n0+g)*SSTRIDE + k8 + t  ]);
                b[j][1] = __float_as_uint(Bs_[(n0+g)*SSTRIDE + k8 + t+4]);
            }
            #pragma unroll
            for (int i = 0; i < 4; i++)
                #pragma unroll
                for (int j = 0; j < 8; j++)
                    MMA_TF32(c[i][j], a[i], b[j]);
        }
        __syncthreads();
        buf ^= 1;
    }

    #pragma unroll
    for (int i = 0; i < 4; i++) {
        size_t r0 = row0 + wm + 16*i + g;
        size_t r1 = r0 + 8;
        #pragma unroll
        for (int j = 0; j < 8; j++) {
            int cb = (int)col0 + wn + 8*j + 2*t;
            float b0 = bias[cb], b1 = bias[cb+1];
            float v0 = c[i][j][0] + b0, v1 = c[i][j][1] + b1;
            float v2 = c[i][j][2] + b0, v3 = c[i][j][3] + b1;
            if (EPI == EPI_RES) {
                float2 ra = *(const float2*)&res[r0*N + cb];
                float2 rb = *(const float2*)&res[r1*N + cb];
                v0 += ra.x; v1 += ra.y; v2 += rb.x; v3 += rb.y;
            }
            if (EPI == EPI_GELU) {
                v0 = f2tf32(gelu_f(v0)); v1 = f2tf32(gelu_f(v1));
                v2 = f2tf32(gelu_f(v2)); v3 = f2tf32(gelu_f(v3));
            }
            *(float2*)&C[r0*N + cb] = make_float2(v0, v1);
            *(float2*)&C[r1*N + cb] = make_float2(v2, v3);
        }
    }
}

// ---------------- attention GEMM 1: S = Q @ K^T (batched over b,h) -----------
// tile 128x128, K=64 entirely in smem, edge rows clamped to SEQ_-1.
__global__ __launch_bounds__(128, 2)
void qk_k(const float* __restrict__ qkv, float* __restrict__ S)
{
    extern __shared__ float sm[];
    float* As = sm;                 // [128][68]
    float* Bs = sm + 128*68;        // [128][68]
    const int tid  = threadIdx.x;
    const int lane = tid & 31, wid = tid >> 5;
    const int wm = (wid >> 1) * 64, wn = (wid & 1) * 64;
    const int g = lane >> 2, t = lane & 3;
    const int row0 = blockIdx.y * 128, col0 = blockIdx.x * 128;
    const int bh = blockIdx.z, b = bh / H_, h = bh % H_;
    const float* Qb = qkv + (size_t)b*SEQ_*QKV_N + h*HD_;
    const float* Kb = Qb + D_;
    float* C = S + (size_t)bh * (SP_*SP_);

    const int lr = tid >> 3;         // 0..15
    const int kc = (tid & 7) * 8;    // 0..56

    #pragma unroll
    for (int it = 0; it < 8; it++) {
        int r = lr + 16*it;
        int q  = min(row0 + r, SEQ_-1);
        int kk = min(col0 + r, SEQ_-1);
        const float4* qa = (const float4*)(Qb + (size_t)q*QKV_N + kc);
        const float4* ka = (const float4*)(Kb + (size_t)kk*QKV_N + kc);
        float4 a0 = qa[0], a1 = qa[1], b0 = ka[0], b1 = ka[1];
        a0.x=f2tf32(a0.x); a0.y=f2tf32(a0.y); a0.z=f2tf32(a0.z); a0.w=f2tf32(a0.w);
        a1.x=f2tf32(a1.x); a1.y=f2tf32(a1.y); a1.z=f2tf32(a1.z); a1.w=f2tf32(a1.w);
        b0.x=f2tf32(b0.x); b0.y=f2tf32(b0.y); b0.z=f2tf32(b0.z); b0.w=f2tf32(b0.w);
        b1.x=f2tf32(b1.x); b1.y=f2tf32(b1.y); b1.z=f2tf32(b1.z); b1.w=f2tf32(b1.w);
        *(float4*)(As + r*68 + kc)     = a0;
        *(float4*)(As + r*68 + kc + 4) = a1;
        *(float4*)(Bs + r*68 + kc)     = b0;
        *(float4*)(Bs + r*68 + kc + 4) = b1;
    }
    __syncthreads();

    float c[4][8][4];
    #pragma unroll
    for (int i = 0; i < 4; i++)
        #pragma unroll
        for (int j = 0; j < 8; j++)
            #pragma unroll
            for (int f = 0; f < 4; f++) c[i][j][f] = 0.f;

    #pragma unroll
    for (int ks = 0; ks < 8; ks++) {
        const int k8 = ks * 8;
        u32 a[4][4], bb[8][2];
        #pragma unroll
        for (int i = 0; i < 4; i++) {
            int m0 = wm + 16*i;
            a[i][0] = __float_as_uint(As[(m0+g  )*68 + k8 + t  ]);
            a[i][1] = __float_as_uint(As[(m0+g+8)*68 + k8 + t  ]);
            a[i][2] = __float_as_uint(As[(m0+g  )*68 + k8 + t+4]);
            a[i][3] = __float_as_uint(As[(m0+g+8)*68 + k8 + t+4]);
        }
        #pragma unroll
        for (int j = 0; j < 8; j++) {
            int n0 = wn + 8*j;
            bb[j][0] = __float_as_uint(Bs[(n0+g)*68 + k8 + t  ]);
            bb[j][1] = __float_as_uint(Bs[(n0+g)*68 + k8 + t+4]);
        }
        #pragma unroll
        for (int i = 0; i < 4; i++)
            #pragma unroll
            for (int j = 0; j < 8; j++)
                MMA_TF32(c[i][j], a[i], bb[j]);
    }

    #pragma unroll
    for (int i = 0; i < 4; i++) {
        size_t r0 = (size_t)(row0 + wm + 16*i + g);
        size_t r1 = r0 + 8;
        #pragma unroll
        for (int j = 0; j < 8; j++) {
            int cb = col0 + wn + 8*j + 2*t;
            *(float2*)&C[r0*SP_ + cb] = make_float2(c[i][j][0], c[i][j][1]);
            *(float2*)&C[r1*SP_ + cb] = make_float2(c[i][j][2], c[i][j][3]);
        }
    }
}

// ---------------- softmax over score rows (in place, emits tf32 P) -----------
__global__ __launch_bounds__(256)
void smax_k(float* __restrict__ S)
{
    const int q = blockIdx.x;          // 0..1024
    const int bh = blockIdx.y;
    float* row = S + (size_t)bh*(SP_*SP_) + (size_t)q*SP_;
    const int tid = threadIdx.x;
    __shared__ float red[256];

    float v[5];
    float mx = -1e30f;
    #pragma unroll
    for (int i = 0; i < 5; i++) {
        int j = tid + 256*i;
        v[i] = (j < SEQ_) ? row[j] * 0.125f : -1e30f;
        mx = fmaxf(mx, v[i]);
    }
    red[tid] = mx; __syncthreads();
    for (int o = 128; o > 0; o >>= 1) { if (tid < o) red[tid] = fmaxf(red[tid], red[tid+o]); __syncthreads(); }
    mx = red[0]; __syncthreads();

    float e[5];
    float s = 0.f;
    #pragma unroll
    for (int i = 0; i < 5; i++) {
        int j = tid + 256*i;
        e[i] = (j < SEQ_) ? __expf(v[i] - mx) : 0.f;
        s += e[i];
    }
    red[tid] = s; __syncthreads();
    for (int o = 128; o > 0; o >>= 1) { if (tid < o) red[tid] += red[tid+o]; __syncthreads(); }
    float inv = 1.f / red[0];

    #pragma unroll
    for (int i = 0; i < 5; i++) {
        int j = tid + 256*i;
        if (j < SEQ_) row[j] = f2tf32(e[i] * inv);
    }
    if (tid < KP_ - SEQ_) row[SEQ_ + tid] = 0.f;   // zero pad 1025..1055
}

// ---------------- V transpose: vT[bh][d][j] = qkv V section ------------------
__global__ void vt_k(const float* __restrict__ qkv, float* __restrict__ vT)
{
    int idx = blockIdx.x*blockDim.x + threadIdx.x;
    if (idx >= 48*SEQ_*HD_) return;
    int d = idx & 63;
    int tt = idx >> 6;
    int j = tt % SEQ_;
    int bh = tt / SEQ_;
    int b = bh / H_, h = bh % H_;
    vT[(size_t)bh*HD_*KP_ + (size_t)d*KP_ + j] =
        f2tf32(qkv[((size_t)b*SEQ_ + j)*QKV_N + 2*D_ + h*HD_ + d]);
}

// ---------------- attention GEMM 2: O = P @ V^T (tile 128x64, K=1056) --------
#define PVA 4608            // A stage floats (128*36)
#define PVB 2304            // B stage floats (64*36)
__global__ __launch_bounds__(128, 2)
void pv_k(const float* __restrict__ S, const float* __restrict__ vT,
          float* __restrict__ attn)
{
    extern __shared__ float sm[];
    // layout: A0 | A1 | B0 | B1
    const int tid  = threadIdx.x;
    const int lane = tid & 31, wid = tid >> 5;
    const int wm = (wid >> 1) * 64, wn = (wid & 1) * 32;
    const int g = lane >> 2, t = lane & 3;
    const int row0 = blockIdx.x * 128;
    const int bh = blockIdx.y, b = bh / H_, h = bh % H_;
    const float* Ab = S + (size_t)bh*(SP_*SP_);
    const float* Bb = vT + (size_t)bh*HD_*KP_;

    const int lr = tid >> 3;
    const int lk = (tid & 7) * 4;
    const float* Aptr = Ab + (size_t)(row0 + lr)*SP_ + lk;
    const float* Bptr = Bb + (size_t)lr*KP_ + lk;
    const u32 sb = smem_u32(sm);
    const u32 da = (u32)(lr*SSTRIDE + lk)*4;

    float c[4][4][4];
    #pragma unroll
    for (int i = 0; i < 4; i++)
        #pragma unroll
        for (int j = 0; j < 4; j++)
            #pragma unroll
            for (int f = 0; f < 4; f++) c[i][j][f] = 0.f;

    {
        #pragma unroll
        for (int it = 0; it < 8; it++)
            CP16(sb + da + it*16*SSTRIDE*4, Aptr + (size_t)it*16*SP_);
        #pragma unroll
        for (int it = 0; it < 4; it++)
            CP16(sb + 2*PVA*4 + da + it*16*SSTRIDE*4, Bptr + (size_t)it*16*KP_);
        CP_COMMIT();
    }

    int buf = 0;
    for (int kt = 0; kt < 33; kt++) {
        CP_WAIT0();
        __syncthreads();
        if (kt + 1 < 33) {
            int k0 = (kt + 1) << 5;
            u32 ad = sb + (buf^1)*PVA*4 + da;
            u32 bd = sb + (2*PVA + (buf^1)*PVB)*4 + da;
            #pragma unroll
            for (int it = 0; it < 8; it++)
                CP16(ad + it*16*SSTRIDE*4, Aptr + k0 + (size_t)it*16*SP_);
            #pragma unroll
            for (int it = 0; it < 4; it++)
                CP16(bd + it*16*SSTRIDE*4, Bptr + k0 + (size_t)it*16*KP_);
            CP_COMMIT();
        }
        const float* As_ = sm + buf*PVA;
        const float* Bs_ = sm + 2*PVA + buf*PVB;
        #pragma unroll
        for (int ks = 0; ks < 4; ks++) {
            const int k8 = ks * 8;
            u32 a[4][4], bb[4][2];
            #pragma unroll
            for (int i = 0; i < 4; i++) {
                int m0 = wm + 16*i;
                a[i][0] = __float_as_uint(As_[(m0+g  )*SSTRIDE + k8 + t  ]);
                a[i][1] = __float_as_uint(As_[(m0+g+8)*SSTRIDE + k8 + t  ]);
                a[i][2] = __float_as_uint(As_[(m0+g  )*SSTRIDE + k8 + t+4]);
                a[i][3] = __float_as_uint(As_[(m0+g+8)*SSTRIDE + k8 + t+4]);
            }
            #pragma unroll
            for (int j = 0; j < 4; j++) {
                int n0 = wn + 8*j;
                bb[j][0] = __float_as_uint(Bs_[(n0+g)*SSTRIDE + k8 + t  ]);
                bb[j][1] = __float_as_uint(Bs_[(n0+g)*SSTRIDE + k8 + t+4]);
            }
            #pragma unroll
            for (int i = 0; i < 4; i++)
                #pragma unroll
                for (int j = 0; j < 4; j++)
                    MMA_TF32(c[i][j], a[i], bb[j]);
        }
        __syncthreads();
        buf ^= 1;
    }

    #pragma unroll
    for (int i = 0; i < 4; i++) {
        int r0 = row0 + wm + 16*i + g;
        int r1 = r0 + 8;
        #pragma unroll
        for (int j = 0; j < 4; j++) {
            int cb = wn + 8*j + 2*t;
            if (r0 < SEQ_) {
                size_t o = ((size_t)b*SEQ_ + r0)*D_ + h*HD_ + cb;
                *(float2*)&attn[o] = make_float2(f2tf32(c[i][j][0]), f2tf32(c[i][j][1]));
            }
            if (r1 < SEQ_) {
                size_t o = ((size_t)b*SEQ_ + r1)*D_ + h*HD_ + cb;
                *(float2*)&attn[o] = make_float2(f2tf32(c[i][j][2]), f2tf32(c[i][j][3]));
            }
        }
    }
}

// ---------------- layernorm: emits tf32-rounded fp32 -------------------------
__global__ void ln_k(const float* __restrict__ x, const float* __restrict__ g,
                     const float* __restrict__ b, float* __restrict__ y)
{
    int row = blockIdx.x;
    int tid = threadIdx.x;
    const float* xr = x + (size_t)row*D_;
    float v[3];
    float s = 0.f;
    #pragma unroll
    for (int i = 0; i < 3; i++) { v[i] = xr[tid + 128*i]; s += v[i]; }
    __shared__ float red[128];
    red[tid] = s; __syncthreads();
    for (int o = 64; o > 0; o >>= 1) { if (tid < o) red[tid] += red[tid+o]; __syncthreads(); }
    float mu = red[0] * (1.f/D_);
    __syncthreads();
    float s2 = 0.f;
    #pragma unroll
    for (int i = 0; i < 3; i++) { float d = v[i]-mu; s2 += d*d; }
    red[tid] = s2; __syncthreads();
    for (int o = 64; o > 0; o >>= 1) { if (tid < o) red[tid] += red[tid+o]; __syncthreads(); }
    float inv = rsqrtf(red[0]*(1.f/D_) + 1e-5f);
    float* yr = y + (size_t)row*D_;
    #pragma unroll
    for (int i = 0; i < 3; i++) {
        int c = tid + 128*i;
        yr[c] = f2tf32((v[i]-mu)*inv*g[c] + b[c]);
    }
}

// ---------------- patch-embed assemble ---------------------------------------
__global__ void assemble_k(const float* __restrict__ tmp, const float* __restrict__ cls,
                           float* __restrict__ x)
{
    int idx = blockIdx.x*blockDim.x + threadIdx.x;
    if (idx >= ROWS_*D_) return;
    int d = idx % D_;
    int rp = idx / D_;
    int pos = rp % SEQ_;
    int b = rp / SEQ_;
    float val = (pos == 0) ? cls[d] : tmp[((size_t)b*N_ + pos-1)*D_ + d];
    float expo = (float)(d & ~1) * (1.f/(float)D_);
    float ang = (float)pos / powf(10000.f, expo);
    float pe = (d & 1) ? cosf(ang) : sinf(ang);
    x[idx] = val + pe;
}

// ---------------- all weight prep in ONE kernel ------------------------------
#define T1_ (L_*QKV_N*D_)
#define T2_ (L_*D_*D_)
#define T3_ (L_*FF_*D_)
#define T4_ (L_*D_*FF_)
#define T5_ (D_*256)
#define T6_ (L_*QKV_N)
__global__ void prep_k(const float* __restrict__ wq, const float* __restrict__ wk,
                       const float* __restrict__ wv, const float* __restrict__ bq,
                       const float* __restrict__ bk, const float* __restrict__ bv,
                       const float* __restrict__ wo, const float* __restrict__ w1,
                       const float* __restrict__ w2, const float* __restrict__ pat,
                       float* __restrict__ qkvT, float* __restrict__ woT,
                       float* __restrict__ w1T, float* __restrict__ w2T,
                       float* __restrict__ patT, float* __restrict__ pb)
{
    int idx = blockIdx.x*blockDim.x + threadIdx.x;
    if (idx < T1_) {
        int k = idx % D_; int r = idx / D_; int n = r % QKV_N; int l = r / QKV_N;
        int sec = n / D_, jj = n % D_, h = jj >> 6, e = jj & 63;
        const float* w = (sec == 0) ? wq : (sec == 1) ? wk : wv;
        qkvT[idx] = f2tf32(w[(((size_t)l*H_ + h)*D_ + k)*HD_ + e]);
    } else if (idx < T1_+T2_) {
        int i = idx - T1_;
        int k = i % D_; int r = i / D_; int n = r % D_; int l = r / D_;
        woT[i] = f2tf32(wo[((size_t)l*D_ + k)*D_ + n]);
    } else if (idx < T1_+T2_+T3_) {
        int i = idx - (T1_+T2_);
        int k = i % D_; int r = i / D_; int n = r % FF_; int l = r / FF_;
        w1T[i] = f2tf32(w1[((size_t)l*D_ + k)*FF_ + n]);
    } else if (idx < T1_+T2_+T3_+T4_) {
        int i = idx - (T1_+T2_+T3_);
        int k = i % FF_; int r = i / FF_; int n = r % D_; int l = r / D_;
        w2T[i] = f2tf32(w2[((size_t)l*FF_ + k)*D_ + n]);
    } else if (idx < T1_+T2_+T3_+T4_+T5_) {
        int i = idx - (T1_+T2_+T3_+T4_);
        int k = i % 256; int n = i / 256;
        patT[i] = f2tf32(pat[(size_t)k*D_ + n]);
    } else if (idx < T1_+T2_+T3_+T4_+T5_+T6_) {
        int i = idx - (T1_+T2_+T3_+T4_+T5_);
        int n = i % QKV_N; int l = i / QKV_N;
        int sec = n / D_, jj = n % D_, h = jj >> 6, e = jj & 63;
        const float* bb = (sec == 0) ? bq : (sec == 1) ? bk : bv;
        pb[i] = bb[((size_t)l*H_ + h)*HD_ + e];
    }
}

// ---------------- plain tf32 round -------------------------------------------
__global__ void rnd_k(const float* __restrict__ src, float* __restrict__ dst, int total)
{
    int idx = blockIdx.x*blockDim.x + threadIdx.x;
    if (idx >= total) return;
    dst[idx] = f2tf32(src[idx]);
}

// ---------------- classifier logits (NC=2) -----------------------------------
__global__ void logits_k(const float* __restrict__ x, const float* __restrict__ cw,
                         const float* __restrict__ cb, float* __restrict__ lg)
{
    int idx = blockIdx.x*blockDim.x + threadIdx.x;
    if (idx >= B_*N_*NC_) return;
    int c = idx & 1;
    int bn = idx >> 1;
    int n = bn % N_, b = bn / N_;
    const float4* xr = (const float4*)(x + ((size_t)b*SEQ_ + n + 1)*D_);
    float s = cb[c];
    #pragma unroll 4
    for (int d4 = 0; d4 < D_/4; d4++) {
        float4 xv = xr[d4];
        s += xv.x*cw[(d4*4+0)*NC_ + c] + xv.y*cw[(d4*4+1)*NC_ + c]
           + xv.z*cw[(d4*4+2)*NC_ + c] + xv.w*cw[(d4*4+3)*NC_ + c];
    }
    lg[idx] = s;
}

// ---------------- deconv upsample ---------------------------------------------
__global__ void up_k(const float* __restrict__ lg, const float* __restrict__ dw,
                     const float* __restrict__ db, float* __restrict__ out)
{
    int idx = blockIdx.x*blockDim.x + threadIdx.x;
    if (idx >= B_*NC_*N_*16*16) return;
    int ww = idx & 15;
    int t = idx >> 4;
    int hh = t & 15; t >>= 4;
    int n = t % N_;  t /= N_;
    int o = t & 1;   int b = t >> 1;
    float s = db[o];
    #pragma unroll
    for (int c = 0; c < NC_; c++)
        s += lg[((size_t)b*N_ + n)*NC_ + c] * dw[((c*NC_ + o)*16 + hh)*16 + ww];
    out[idx] = s;
}

// ---------------- launch ------------------------------------------------------
extern "C" void kernel_launch(void* const* d_in, const int* in_sizes, int n_in,
                              void* d_out, int out_size)
{
    const float* images  = (const float*)d_in[0];
    const float* patch_w = (const float*)d_in[2];
    const float* patch_b = (const float*)d_in[3];
    const float* cls_tok = (const float*)d_in[4];
    const float* ln1_g   = (const float*)d_in[5];
    const float* ln1_b   = (const float*)d_in[6];
    const float* wq      = (const float*)d_in[7];
    const float* bq      = (const float*)d_in[8];
    const float* wk      = (const float*)d_in[9];
    const float* bk      = (const float*)d_in[10];
    const float* wv      = (const float*)d_in[11];
    const float* bv      = (const float*)d_in[12];
    const float* wo      = (const float*)d_in[13];
    const float* bo      = (const float*)d_in[14];
    const float* ln2_g   = (const float*)d_in[15];
    const float* ln2_b   = (const float*)d_in[16];
    const float* w1      = (const float*)d_in[17];
    const float* b1      = (const float*)d_in[18];
    const float* w2      = (const float*)d_in[19];
    const float* b2      = (const float*)d_in[20];
    const float* cls_w   = (const float*)d_in[21];
    const float* cls_b   = (const float*)d_in[22];
    const float* dc_w    = (const float*)d_in[23];
    const float* dc_b    = (const float*)d_in[24];
    float* out = (float*)d_out;

    float *x, *h, *qkv, *attn, *mlp, *pb, *lg;
    float *qkvT, *woT, *w1T, *w2T, *patT, *img, *S, *vT;
    cudaGetSymbolAddress((void**)&x,    g_x);
    cudaGetSymbolAddress((void**)&h,    g_h);
    cudaGetSymbolAddress((void**)&qkv,  g_qkv);
    cudaGetSymbolAddress((void**)&attn, g_attn);
    cudaGetSymbolAddress((void**)&mlp,  g_mlp);
    cudaGetSymbolAddress((void**)&pb,   g_pb);
    cudaGetSymbolAddress((void**)&qkvT, g_qkvT);
    cudaGetSymbolAddress((void**)&woT,  g_woT);
    cudaGetSymbolAddress((void**)&w1T,  g_w1T);
    cudaGetSymbolAddress((void**)&w2T,  g_w2T);
    cudaGetSymbolAddress((void**)&patT, g_patT);
    cudaGetSymbolAddress((void**)&img,  g_img);
    cudaGetSymbolAddress((void**)&lg,   g_lg);
    cudaGetSymbolAddress((void**)&S,    g_s);
    cudaGetSymbolAddress((void**)&vT,   g_vT);

    const int SMEM_G  = 4*SBUF*4;           // gemm4: 73728 B
    const int SMEM_QK = 2*128*68*4;         // qk:    69632 B
    const int SMEM_PV = (2*PVA + 2*PVB)*4;  // pv:    55296 B
    cudaFuncSetAttribute(gemm4_k<EPI_BIAS>, cudaFuncAttributeMaxDynamicSharedMemorySize, SMEM_G);
    cudaFuncSetAttribute(gemm4_k<EPI_RES>,  cudaFuncAttributeMaxDynamicSharedMemorySize, SMEM_G);
    cudaFuncSetAttribute(gemm4_k<EPI_GELU>, cudaFuncAttributeMaxDynamicSharedMemorySize, SMEM_G);
    cudaFuncSetAttribute(qk_k, cudaFuncAttributeMaxDynamicSharedMemorySize, SMEM_QK);
    cudaFuncSetAttribute(pv_k, cudaFuncAttributeMaxDynamicSharedMemorySize, SMEM_PV);

    // 1. all weight prep (one kernel)
    {
        int total = T1_+T2_+T3_+T4_+T5_+T6_;
        prep_k<<<(total + 255)/256, 256>>>(wq, wk, wv, bq, bk, bv, wo, w1, w2,
                                           patch_w, qkvT, woT, w1T, w2T, patT, pb);
    }
    // 2. image round
    rnd_k<<<(B_*N_*256 + 255)/256, 256>>>(images, img, B_*N_*256);
    // 3. patch embed GEMM
    {
        dim3 g(D_/128, (B_*N_)/128);
        gemm4_k<EPI_BIAS><<<g, 128, SMEM_G>>>(img, patT, patch_b, nullptr, qkv,
                                              B_*N_, D_, 256);
    }
    // 4. assemble (cls + positional encoding)
    assemble_k<<<(ROWS_*D_ + 255)/256, 256>>>(qkv, cls_tok, x);

    dim3 gq(QKV_N/128, ROWSP_/128);
    dim3 go(D_/128,    ROWSP_/128);
    dim3 g1(FF_/128,   ROWSP_/128);
    dim3 gqk(SP_/128, SP_/128, B_*H_);
    dim3 gsm(SEQ_, B_*H_);
    dim3 gpv(SP_/128, B_*H_);

    for (int l = 0; l < L_; l++) {
        ln_k<<<ROWS_, 128>>>(x, ln1_g + l*D_, ln1_b + l*D_, h);             // 5 (l=0)
        gemm4_k<EPI_BIAS><<<gq, 128, SMEM_G>>>(h, qkvT + (size_t)l*QKV_N*D_,
                                               pb + l*QKV_N, nullptr,
                                               qkv, ROWSP_, QKV_N, D_);     // 6 <- profiled
        qk_k<<<gqk, 128, SMEM_QK>>>(qkv, S);
        vt_k<<<(48*SEQ_*HD_ + 255)/256, 256>>>(qkv, vT);
        smax_k<<<gsm, 256>>>(S);
        pv_k<<<gpv, 128, SMEM_PV>>>(S, vT, attn);
        gemm4_k<EPI_RES><<<go, 128, SMEM_G>>>(attn, woT + (size_t)l*D_*D_,
                                              bo + l*D_, x,
                                              x, ROWSP_, D_, D_);
        ln_k<<<ROWS_, 128>>>(x, ln2_g + l*D_, ln2_b + l*D_, h);
        gemm4_k<EPI_GELU><<<g1, 128, SMEM_G>>>(h, w1T + (size_t)l*FF_*D_,
                                               b1 + l*FF_, nullptr,
                                               mlp, ROWSP_, FF_, D_);
        gemm4_k<EPI_RES><<<go, 128, SMEM_G>>>(mlp, w2T + (size_t)l*D_*FF_,
                                              b2 + l*D_, x,
                                              x, ROWSP_, D_, FF_);
    }

    logits_k<<<(B_*N_*NC_ + 127)/128, 128>>>(x, cls_w, cls_b, lg);
    up_k<<<(B_*NC_*N_*256 + 255)/256, 256>>>(lg, dc_w, dc_b, out);
    (void)in_sizes; (void)n_in; (void)out_size;
}

// round 8
// speedup vs baseline: 3.1710x; 1.1682x over previous
#include <cuda_runtime.h>
#include <cuda_bf16.h>
#include <math.h>
#include <stdint.h>

// ---------------- problem constants ----------------
#define D_     384
#define H_     6
#define HD_    64
#define L_     4
#define B_     8
#define N_     1024
#define SEQ_   1025
#define ROWS_  (B_*SEQ_)     // 8200
#define ROWSP_ 8320          // padded: no M predicates in weight GEMMs
#define NC_    2
#define QKV_N  (3*D_)        // 1152
#define FF_    (4*D_)        // 1536
#define SP_    1152          // padded seq (9*128) for attention GEMMs
#define KP_    1056          // padded key-K for P@V (33*32)

typedef unsigned long long u64;
typedef unsigned int u32;

__device__ __forceinline__ float f2tf32(float f) {
    u32 u; asm("cvt.rna.tf32.f32 %0, %1;" : "=r"(u) : "f"(f));
    return __uint_as_float(u);
}

#define MMA_TF32(c, a, b) \
    asm("mma.sync.aligned.m16n8k8.row.col.f32.tf32.tf32.f32 " \
        "{%0,%1,%2,%3}, {%4,%5,%6,%7}, {%8,%9}, {%0,%1,%2,%3};" \
        : "+f"(c[0]), "+f"(c[1]), "+f"(c[2]), "+f"(c[3]) \
        : "r"(a[0]), "r"(a[1]), "r"(a[2]), "r"(a[3]), "r"(b[0]), "r"(b[1]))

#define CP16(saddr, gptr) \
    asm volatile("cp.async.ca.shared.global [%0], [%1], 16;" :: "r"(saddr), "l"(gptr))
#define CP_COMMIT() asm volatile("cp.async.commit_group;" ::: "memory")
#define CP_WAIT0()  asm volatile("cp.async.wait_group 0;" ::: "memory")

__device__ __forceinline__ u32 smem_u32(const void* p) {
    u32 a;
    asm("{ .reg .u64 t; cvta.to.shared.u64 t, %1; cvt.u32.u64 %0, t; }" : "=r"(a) : "l"(p));
    return a;
}

// ---------------- scratch (device globals; no allocation allowed) ----------
__device__ float g_x[ROWSP_*D_];
__device__ float g_h[ROWSP_*D_];
__device__ float g_qkv[ROWSP_*QKV_N];
__device__ float g_attn[ROWSP_*D_];
__device__ float g_mlp[ROWSP_*FF_];
__device__ float g_pb[L_*QKV_N];
__device__ float g_qkvT[L_*QKV_N*D_];
__device__ float g_woT[L_*D_*D_];
__device__ float g_w1T[L_*FF_*D_];
__device__ float g_w2T[L_*D_*FF_];
__device__ float g_patT[D_*256];
__device__ float g_img[B_*N_*256];
__device__ float g_lg[B_*N_*NC_];
__device__ float g_s[48*SP_*SP_];     // attention probs (unnormalized)
__device__ float g_vT[48*HD_*KP_];    // V transposed per (b,h)

// ---------------- GEMM v4 (tf32 mma, 64x64 warp tiles, cp.async) -------------
#define EPI_BIAS 0
#define EPI_RES  1
#define EPI_GELU 2
#define SSTRIDE 36
#define SBUF    (128*SSTRIDE)

__device__ __forceinline__ float gelu_f(float v) {
    return 0.5f * v * (1.f + erff(v * 0.70710678118654752f));
}

template<int EPI>
__global__ __launch_bounds__(128, 2)
void gemm4_k(const float* __restrict__ A, const float* __restrict__ Bm,
             const float* __restrict__ bias, const float* __restrict__ res,
             float* __restrict__ C, int M, int N, int K)
{
    extern __shared__ float sm[];
    const int tid  = threadIdx.x;
    const int lane = tid & 31, wid = tid >> 5;
    const int wm = (wid >> 1) * 64, wn = (wid & 1) * 64;
    const int g = lane >> 2, t = lane & 3;
    const size_t row0 = (size_t)blockIdx.y * 128;
    const size_t col0 = (size_t)blockIdx.x * 128;

    const int lr = tid >> 3;
    const int lk = (tid & 7) * 4;

    const float* Aptr = A + (row0 + lr) * K + lk;
    const float* Bptr = Bm + (col0 + lr) * K + lk;
    const u32 asb0 = smem_u32(sm);
    const u32 dst_off = (u32)(lr * SSTRIDE + lk) * 4;

    float c[4][8][4];
    #pragma unroll
    for (int i = 0; i < 4; i++)
        #pragma unroll
        for (int j = 0; j < 8; j++)
            #pragma unroll
            for (int f = 0; f < 4; f++) c[i][j][f] = 0.f;

    const int KT = K >> 5;

    {
        u32 ad = asb0 + dst_off;
        u32 bd = asb0 + 2*SBUF*4 + dst_off;
        #pragma unroll
        for (int it = 0; it < 8; it++) {
            CP16(ad + it*16*SSTRIDE*4, Aptr + (size_t)it*16*K);
            CP16(bd + it*16*SSTRIDE*4, Bptr + (size_t)it*16*K);
        }
        CP_COMMIT();
    }

    int buf = 0;
    for (int kt = 0; kt < KT; kt++) {
        CP_WAIT0();
        __syncthreads();
        if (kt + 1 < KT) {
            int k0 = (kt + 1) << 5;
            u32 ad = asb0 + (buf^1)*SBUF*4 + dst_off;
            u32 bd = asb0 + (2 + (buf^1))*SBUF*4 + dst_off;
            #pragma unroll
            for (int it = 0; it < 8; it++) {
                CP16(ad + it*16*SSTRIDE*4, Aptr + k0 + (size_t)it*16*K);
                CP16(bd + it*16*SSTRIDE*4, Bptr + k0 + (size_t)it*16*K);
            }
            CP_COMMIT();
        }
        const float* As_ = sm + buf*SBUF;
        const float* Bs_ = sm + (2 + buf)*SBUF;
        #pragma unroll
        for (int ks = 0; ks < 4; ks++) {
            const int k8 = ks * 8;
            u32 a[4][4], b[8][2];
            #pragma unroll
            for (int i = 0; i < 4; i++) {
                int m0 = wm + 16*i;
                a[i][0] = __float_as_uint(As_[(m0+g  )*SSTRIDE + k8 + t  ]);
                a[i][1] = __float_as_uint(As_[(m0+g+8)*SSTRIDE + k8 + t  ]);
                a[i][2] = __float_as_uint(As_[(m0+g  )*SSTRIDE + k8 + t+4]);
                a[i][3] = __float_as_uint(As_[(m0+g+8)*SSTRIDE + k8 + t+4]);
            }
            #pragma unroll
            for (int j = 0; j < 8; j++) {
                int n0 = wn + 8*j;
                b[j][0] = __float_as_uint(Bs_[(n0+g)*SSTRIDE + k8 + t  ]);
                b[j][1] = __float_as_uint(Bs_[(n0+g)*SSTRIDE + k8 + t+4]);
            }
            #pragma unroll
            for (int i = 0; i < 4; i++)
                #pragma unroll
                for (int j = 0; j < 8; j++)
                    MMA_TF32(c[i][j], a[i], b[j]);
        }
        __syncthreads();
        buf ^= 1;
    }

    #pragma unroll
    for (int i = 0; i < 4; i++) {
        size_t r0 = row0 + wm + 16*i + g;
        size_t r1 = r0 + 8;
        #pragma unroll
        for (int j = 0; j < 8; j++) {
            int cb = (int)col0 + wn + 8*j + 2*t;
            float b0 = bias[cb], b1 = bias[cb+1];
            float v0 = c[i][j][0] + b0, v1 = c[i][j][1] + b1;
            float v2 = c[i][j][2] + b0, v3 = c[i][j][3] + b1;
            if (EPI == EPI_RES) {
                float2 ra = *(const float2*)&res[r0*N + cb];
                float2 rb = *(const float2*)&res[r1*N + cb];
                v0 += ra.x; v1 += ra.y; v2 += rb.x; v3 += rb.y;
            }
            if (EPI == EPI_GELU) {
                v0 = f2tf32(gelu_f(v0)); v1 = f2tf32(gelu_f(v1));
                v2 = f2tf32(gelu_f(v2)); v3 = f2tf32(gelu_f(v3));
            }
            *(float2*)&C[r0*N + cb] = make_float2(v0, v1);
            *(float2*)&C[r1*N + cb] = make_float2(v2, v3);
        }
    }
}

// ---------------- attention GEMM 1: P = exp(Q @ K^T / 8), unnormalized -------
// tile 128x128, K=64 in smem, edge rows clamped; pad cols >= SEQ_ zeroed.
__global__ __launch_bounds__(128, 2)
void qk_k(const float* __restrict__ qkv, float* __restrict__ S)
{
    extern __shared__ float sm[];
    float* As = sm;                 // [128][68]
    float* Bs = sm + 128*68;        // [128][68]
    const int tid  = threadIdx.x;
    const int lane = tid & 31, wid = tid >> 5;
    const int wm = (wid >> 1) * 64, wn = (wid & 1) * 64;
    const int g = lane >> 2, t = lane & 3;
    const int row0 = blockIdx.y * 128, col0 = blockIdx.x * 128;
    const int bh = blockIdx.z, b = bh / H_, h = bh % H_;
    const float* Qb = qkv + (size_t)b*SEQ_*QKV_N + h*HD_;
    const float* Kb = Qb + D_;
    float* C = S + (size_t)bh * (SP_*SP_);

    const int lr = tid >> 3;         // 0..15
    const int kc = (tid & 7) * 8;    // 0..56

    #pragma unroll
    for (int it = 0; it < 8; it++) {
        int r = lr + 16*it;
        int q  = min(row0 + r, SEQ_-1);
        int kk = min(col0 + r, SEQ_-1);
        const float4* qa = (const float4*)(Qb + (size_t)q*QKV_N + kc);
        const float4* ka = (const float4*)(Kb + (size_t)kk*QKV_N + kc);
        float4 a0 = qa[0], a1 = qa[1], b0 = ka[0], b1 = ka[1];
        a0.x=f2tf32(a0.x); a0.y=f2tf32(a0.y); a0.z=f2tf32(a0.z); a0.w=f2tf32(a0.w);
        a1.x=f2tf32(a1.x); a1.y=f2tf32(a1.y); a1.z=f2tf32(a1.z); a1.w=f2tf32(a1.w);
        b0.x=f2tf32(b0.x); b0.y=f2tf32(b0.y); b0.z=f2tf32(b0.z); b0.w=f2tf32(b0.w);
        b1.x=f2tf32(b1.x); b1.y=f2tf32(b1.y); b1.z=f2tf32(b1.z); b1.w=f2tf32(b1.w);
        *(float4*)(As + r*68 + kc)     = a0;
        *(float4*)(As + r*68 + kc + 4) = a1;
        *(float4*)(Bs + r*68 + kc)     = b0;
        *(float4*)(Bs + r*68 + kc + 4) = b1;
    }
    __syncthreads();

    float c[4][8][4];
    #pragma unroll
    for (int i = 0; i < 4; i++)
        #pragma unroll
        for (int j = 0; j < 8; j++)
            #pragma unroll
            for (int f = 0; f < 4; f++) c[i][j][f] = 0.f;

    #pragma unroll
    for (int ks = 0; ks < 8; ks++) {
        const int k8 = ks * 8;
        u32 a[4][4], bb[8][2];
        #pragma unroll
        for (int i = 0; i < 4; i++) {
            int m0 = wm + 16*i;
            a[i][0] = __float_as_uint(As[(m0+g  )*68 + k8 + t  ]);
            a[i][1] = __float_as_uint(As[(m0+g+8)*68 + k8 + t  ]);
            a[i][2] = __float_as_uint(As[(m0+g  )*68 + k8 + t+4]);
            a[i][3] = __float_as_uint(As[(m0+g+8)*68 + k8 + t+4]);
        }
        #pragma unroll
        for (int j = 0; j < 8; j++) {
            int n0 = wn + 8*j;
            bb[j][0] = __float_as_uint(Bs[(n0+g)*68 + k8 + t  ]);
            bb[j][1] = __float_as_uint(Bs[(n0+g)*68 + k8 + t+4]);
        }
        #pragma unroll
        for (int i = 0; i < 4; i++)
            #pragma unroll
            for (int j = 0; j < 8; j++)
                MMA_TF32(c[i][j], a[i], bb[j]);
    }

    #pragma unroll
    for (int i = 0; i < 4; i++) {
        size_t r0 = (size_t)(row0 + wm + 16*i + g);
        size_t r1 = r0 + 8;
        #pragma unroll
        for (int j = 0; j < 8; j++) {
            int cb = col0 + wn + 8*j + 2*t;
            float p00 = (cb   < SEQ_) ? f2tf32(__expf(c[i][j][0]*0.125f)) : 0.f;
            float p01 = (cb+1 < SEQ_) ? f2tf32(__expf(c[i][j][1]*0.125f)) : 0.f;
            float p10 = (cb   < SEQ_) ? f2tf32(__expf(c[i][j][2]*0.125f)) : 0.f;
            float p11 = (cb+1 < SEQ_) ? f2tf32(__expf(c[i][j][3]*0.125f)) : 0.f;
            *(float2*)&C[r0*SP_ + cb] = make_float2(p00, p01);
            *(float2*)&C[r1*SP_ + cb] = make_float2(p10, p11);
        }
    }
}

// ---------------- V transpose: vT[bh][d][j] = qkv V section ------------------
__global__ void vt_k(const float* __restrict__ qkv, float* __restrict__ vT)
{
    int idx = blockIdx.x*blockDim.x + threadIdx.x;
    if (idx >= 48*SEQ_*HD_) return;
    int d = idx & 63;
    int tt = idx >> 6;
    int j = tt % SEQ_;
    int bh = tt / SEQ_;
    int b = bh / H_, h = bh % H_;
    vT[(size_t)bh*HD_*KP_ + (size_t)d*KP_ + j] =
        f2tf32(qkv[((size_t)b*SEQ_ + j)*QKV_N + 2*D_ + h*HD_ + d]);
}

// ---------------- attention GEMM 2: O = (P @ V^T) / rowsum(P) ----------------
#define PVA 4608            // A stage floats (128*36)
#define PVB 2304            // B stage floats (64*36)
__global__ __launch_bounds__(128, 2)
void pv_k(const float* __restrict__ S, const float* __restrict__ vT,
          float* __restrict__ attn)
{
    extern __shared__ float sm[];
    const int tid  = threadIdx.x;
    const int lane = tid & 31, wid = tid >> 5;
    const int wm = (wid >> 1) * 64, wn = (wid & 1) * 32;
    const int g = lane >> 2, t = lane & 3;
    const int row0 = blockIdx.x * 128;
    const int bh = blockIdx.y, b = bh / H_, h = bh % H_;
    const float* Ab = S + (size_t)bh*(SP_*SP_);
    const float* Bb = vT + (size_t)bh*HD_*KP_;

    const int lr = tid >> 3;
    const int lk = (tid & 7) * 4;
    const float* Aptr = Ab + (size_t)(row0 + lr)*SP_ + lk;
    const float* Bptr = Bb + (size_t)lr*KP_ + lk;
    const u32 sb = smem_u32(sm);
    const u32 da = (u32)(lr*SSTRIDE + lk)*4;

    float c[4][4][4];
    #pragma unroll
    for (int i = 0; i < 4; i++)
        #pragma unroll
        for (int j = 0; j < 4; j++)
            #pragma unroll
            for (int f = 0; f < 4; f++) c[i][j][f] = 0.f;
    float asum[4][2];
    #pragma unroll
    for (int i = 0; i < 4; i++) { asum[i][0] = 0.f; asum[i][1] = 0.f; }

    {
        #pragma unroll
        for (int it = 0; it < 8; it++)
            CP16(sb + da + it*16*SSTRIDE*4, Aptr + (size_t)it*16*SP_);
        #pragma unroll
        for (int it = 0; it < 4; it++)
            CP16(sb + 2*PVA*4 + da + it*16*SSTRIDE*4, Bptr + (size_t)it*16*KP_);
        CP_COMMIT();
    }

    int buf = 0;
    for (int kt = 0; kt < 33; kt++) {
        CP_WAIT0();
        __syncthreads();
        if (kt + 1 < 33) {
            int k0 = (kt + 1) << 5;
            u32 ad = sb + (buf^1)*PVA*4 + da;
            u32 bd = sb + (2*PVA + (buf^1)*PVB)*4 + da;
            #pragma unroll
            for (int it = 0; it < 8; it++)
                CP16(ad + it*16*SSTRIDE*4, Aptr + k0 + (size_t)it*16*SP_);
            #pragma unroll
            for (int it = 0; it < 4; it++)
                CP16(bd + it*16*SSTRIDE*4, Bptr + k0 + (size_t)it*16*KP_);
            CP_COMMIT();
        }
        const float* As_ = sm + buf*PVA;
        const float* Bs_ = sm + 2*PVA + buf*PVB;
        #pragma unroll
        for (int ks = 0; ks < 4; ks++) {
            const int k8 = ks * 8;
            u32 a[4][4], bb[4][2];
            #pragma unroll
            for (int i = 0; i < 4; i++) {
                int m0 = wm + 16*i;
                a[i][0] = __float_as_uint(As_[(m0+g  )*SSTRIDE + k8 + t  ]);
                a[i][1] = __float_as_uint(As_[(m0+g+8)*SSTRIDE + k8 + t  ]);
                a[i][2] = __float_as_uint(As_[(m0+g  )*SSTRIDE + k8 + t+4]);
                a[i][3] = __float_as_uint(As_[(m0+g+8)*SSTRIDE + k8 + t+4]);
                // row-sum contribution (cols k8+t, k8+t+4): quad covers all cols
                asum[i][0] += __uint_as_float(a[i][0]) + __uint_as_float(a[i][2]);
                asum[i][1] += __uint_as_float(a[i][1]) + __uint_as_float(a[i][3]);
            }
            #pragma unroll
            for (int j = 0; j < 4; j++) {
                int n0 = wn + 8*j;
                bb[j][0] = __float_as_uint(Bs_[(n0+g)*SSTRIDE + k8 + t  ]);
                bb[j][1] = __float_as_uint(Bs_[(n0+g)*SSTRIDE + k8 + t+4]);
            }
            #pragma unroll
            for (int i = 0; i < 4; i++)
                #pragma unroll
                for (int j = 0; j < 4; j++)
                    MMA_TF32(c[i][j], a[i], bb[j]);
        }
        __syncthreads();
        buf ^= 1;
    }

    // reduce row sums across the quad (lanes g*4 + t, t=0..3)
    #pragma unroll
    for (int i = 0; i < 4; i++) {
        #pragma unroll
        for (int s = 0; s < 2; s++) {
            float v = asum[i][s];
            v += __shfl_xor_sync(0xffffffffu, v, 1);
            v += __shfl_xor_sync(0xffffffffu, v, 2);
            asum[i][s] = v;
        }
    }

    #pragma unroll
    for (int i = 0; i < 4; i++) {
        int r0 = row0 + wm + 16*i + g;
        int r1 = r0 + 8;
        float inv0 = 1.f / asum[i][0];
        float inv1 = 1.f / asum[i][1];
        #pragma unroll
        for (int j = 0; j < 4; j++) {
            int cb = wn + 8*j + 2*t;
            if (r0 < SEQ_) {
                size_t o = ((size_t)b*SEQ_ + r0)*D_ + h*HD_ + cb;
                *(float2*)&attn[o] = make_float2(f2tf32(c[i][j][0]*inv0),
                                                 f2tf32(c[i][j][1]*inv0));
            }
            if (r1 < SEQ_) {
                size_t o = ((size_t)b*SEQ_ + r1)*D_ + h*HD_ + cb;
                *(float2*)&attn[o] = make_float2(f2tf32(c[i][j][2]*inv1),
                                                 f2tf32(c[i][j][3]*inv1));
            }
        }
    }
}

// ---------------- layernorm: warp per row, shfl reductions -------------------
__global__ __launch_bounds__(256)
void ln_k(const float* __restrict__ x, const float* __restrict__ g,
          const float* __restrict__ b, float* __restrict__ y)
{
    const int w    = threadIdx.x >> 5;
    const int lane = threadIdx.x & 31;
    const int row  = blockIdx.x * 8 + w;
    const float* xr = x + (size_t)row*D_;
    float v[12];
    float s = 0.f;
    #pragma unroll
    for (int i = 0; i < 12; i++) { v[i] = xr[lane + 32*i]; s += v[i]; }
    #pragma unroll
    for (int o = 16; o > 0; o >>= 1) s += __shfl_xor_sync(0xffffffffu, s, o);
    float mu = s * (1.f/D_);
    float s2 = 0.f;
    #pragma unroll
    for (int i = 0; i < 12; i++) { float d = v[i]-mu; s2 += d*d; }
    #pragma unroll
    for (int o = 16; o > 0; o >>= 1) s2 += __shfl_xor_sync(0xffffffffu, s2, o);
    float inv = rsqrtf(s2*(1.f/D_) + 1e-5f);
    float* yr = y + (size_t)row*D_;
    #pragma unroll
    for (int i = 0; i < 12; i++) {
        int c = lane + 32*i;
        yr[c] = f2tf32((v[i]-mu)*inv*g[c] + b[c]);
    }
}

// ---------------- patch-embed assemble ---------------------------------------
__global__ void assemble_k(const float* __restrict__ tmp, const float* __restrict__ cls,
                           float* __restrict__ x)
{
    int idx = blockIdx.x*blockDim.x + threadIdx.x;
    if (idx >= ROWS_*D_) return;
    int d = idx % D_;
    int rp = idx / D_;
    int pos = rp % SEQ_;
    int b = rp / SEQ_;
    float val = (pos == 0) ? cls[d] : tmp[((size_t)b*N_ + pos-1)*D_ + d];
    float expo = (float)(d & ~1) * (1.f/(float)D_);
    float ang = (float)pos / powf(10000.f, expo);
    float pe = (d & 1) ? cosf(ang) : sinf(ang);
    x[idx] = val + pe;
}

// ---------------- all weight prep in ONE kernel ------------------------------
#define T1_ (L_*QKV_N*D_)
#define T2_ (L_*D_*D_)
#define T3_ (L_*FF_*D_)
#define T4_ (L_*D_*FF_)
#define T5_ (D_*256)
#define T6_ (L_*QKV_N)
__global__ void prep_k(const float* __restrict__ wq, const float* __restrict__ wk,
                       const float* __restrict__ wv, const float* __restrict__ bq,
                       const float* __restrict__ bk, const float* __restrict__ bv,
                       const float* __restrict__ wo, const float* __restrict__ w1,
                       const float* __restrict__ w2, const float* __restrict__ pat,
                       float* __restrict__ qkvT, float* __restrict__ woT,
                       float* __restrict__ w1T, float* __restrict__ w2T,
                       float* __restrict__ patT, float* __restrict__ pb)
{
    int idx = blockIdx.x*blockDim.x + threadIdx.x;
    if (idx < T1_) {
        int k = idx % D_; int r = idx / D_; int n = r % QKV_N; int l = r / QKV_N;
        int sec = n / D_, jj = n % D_, h = jj >> 6, e = jj & 63;
        const float* w = (sec == 0) ? wq : (sec == 1) ? wk : wv;
        qkvT[idx] = f2tf32(w[(((size_t)l*H_ + h)*D_ + k)*HD_ + e]);
    } else if (idx < T1_+T2_) {
        int i = idx - T1_;
        int k = i % D_; int r = i / D_; int n = r % D_; int l = r / D_;
        woT[i] = f2tf32(wo[((size_t)l*D_ + k)*D_ + n]);
    } else if (idx < T1_+T2_+T3_) {
        int i = idx - (T1_+T2_);
        int k = i % D_; int r = i / D_; int n = r % FF_; int l = r / FF_;
        w1T[i] = f2tf32(w1[((size_t)l*D_ + k)*FF_ + n]);
    } else if (idx < T1_+T2_+T3_+T4_) {
        int i = idx - (T1_+T2_+T3_);
        int k = i % FF_; int r = i / FF_; int n = r % D_; int l = r / D_;
        w2T[i] = f2tf32(w2[((size_t)l*FF_ + k)*D_ + n]);
    } else if (idx < T1_+T2_+T3_+T4_+T5_) {
        int i = idx - (T1_+T2_+T3_+T4_);
        int k = i % 256; int n = i / 256;
        patT[i] = f2tf32(pat[(size_t)k*D_ + n]);
    } else if (idx < T1_+T2_+T3_+T4_+T5_+T6_) {
        int i = idx - (T1_+T2_+T3_+T4_+T5_);
        int n = i % QKV_N; int l = i / QKV_N;
        int sec = n / D_, jj = n % D_, h = jj >> 6, e = jj & 63;
        const float* bb = (sec == 0) ? bq : (sec == 1) ? bk : bv;
        pb[i] = bb[((size_t)l*H_ + h)*HD_ + e];
    }
}

// ---------------- plain tf32 round -------------------------------------------
__global__ void rnd_k(const float* __restrict__ src, float* __restrict__ dst, int total)
{
    int idx = blockIdx.x*blockDim.x + threadIdx.x;
    if (idx >= total) return;
    dst[idx] = f2tf32(src[idx]);
}

// ---------------- classifier logits (NC=2) -----------------------------------
__global__ void logits_k(const float* __restrict__ x, const float* __restrict__ cw,
                         const float* __restrict__ cb, float* __restrict__ lg)
{
    int idx = blockIdx.x*blockDim.x + threadIdx.x;
    if (idx >= B_*N_*NC_) return;
    int c = idx & 1;
    int bn = idx >> 1;
    int n = bn % N_, b = bn / N_;
    const float4* xr = (const float4*)(x + ((size_t)b*SEQ_ + n + 1)*D_);
    float s = cb[c];
    #pragma unroll 4
    for (int d4 = 0; d4 < D_/4; d4++) {
        float4 xv = xr[d4];
        s += xv.x*cw[(d4*4+0)*NC_ + c] + xv.y*cw[(d4*4+1)*NC_ + c]
           + xv.z*cw[(d4*4+2)*NC_ + c] + xv.w*cw[(d4*4+3)*NC_ + c];
    }
    lg[idx] = s;
}

// ---------------- deconv upsample ---------------------------------------------
__global__ void up_k(const float* __restrict__ lg, const float* __restrict__ dw,
                     const float* __restrict__ db, float* __restrict__ out)
{
    int idx = blockIdx.x*blockDim.x + threadIdx.x;
    if (idx >= B_*NC_*N_*16*16) return;
    int ww = idx & 15;
    int t = idx >> 4;
    int hh = t & 15; t >>= 4;
    int n = t % N_;  t /= N_;
    int o = t & 1;   int b = t >> 1;
    float s = db[o];
    #pragma unroll
    for (int c = 0; c < NC_; c++)
        s += lg[((size_t)b*N_ + n)*NC_ + c] * dw[((c*NC_ + o)*16 + hh)*16 + ww];
    out[idx] = s;
}

// ---------------- launch ------------------------------------------------------
extern "C" void kernel_launch(void* const* d_in, const int* in_sizes, int n_in,
                              void* d_out, int out_size)
{
    const float* images  = (const float*)d_in[0];
    const float* patch_w = (const float*)d_in[2];
    const float* patch_b = (const float*)d_in[3];
    const float* cls_tok = (const float*)d_in[4];
    const float* ln1_g   = (const float*)d_in[5];
    const float* ln1_b   = (const float*)d_in[6];
    const float* wq      = (const float*)d_in[7];
    const float* bq      = (const float*)d_in[8];
    const float* wk      = (const float*)d_in[9];
    const float* bk      = (const float*)d_in[10];
    const float* wv      = (const float*)d_in[11];
    const float* bv      = (const float*)d_in[12];
    const float* wo      = (const float*)d_in[13];
    const float* bo      = (const float*)d_in[14];
    const float* ln2_g   = (const float*)d_in[15];
    const float* ln2_b   = (const float*)d_in[16];
    const float* w1      = (const float*)d_in[17];
    const float* b1      = (const float*)d_in[18];
    const float* w2      = (const float*)d_in[19];
    const float* b2      = (const float*)d_in[20];
    const float* cls_w   = (const float*)d_in[21];
    const float* cls_b   = (const float*)d_in[22];
    const float* dc_w    = (const float*)d_in[23];
    const float* dc_b    = (const float*)d_in[24];
    float* out = (float*)d_out;

    float *x, *h, *qkv, *attn, *mlp, *pb, *lg;
    float *qkvT, *woT, *w1T, *w2T, *patT, *img, *S, *vT;
    cudaGetSymbolAddress((void**)&x,    g_x);
    cudaGetSymbolAddress((void**)&h,    g_h);
    cudaGetSymbolAddress((void**)&qkv,  g_qkv);
    cudaGetSymbolAddress((void**)&attn, g_attn);
    cudaGetSymbolAddress((void**)&mlp,  g_mlp);
    cudaGetSymbolAddress((void**)&pb,   g_pb);
    cudaGetSymbolAddress((void**)&qkvT, g_qkvT);
    cudaGetSymbolAddress((void**)&woT,  g_woT);
    cudaGetSymbolAddress((void**)&w1T,  g_w1T);
    cudaGetSymbolAddress((void**)&w2T,  g_w2T);
    cudaGetSymbolAddress((void**)&patT, g_patT);
    cudaGetSymbolAddress((void**)&img,  g_img);
    cudaGetSymbolAddress((void**)&lg,   g_lg);
    cudaGetSymbolAddress((void**)&S,    g_s);
    cudaGetSymbolAddress((void**)&vT,   g_vT);

    const int SMEM_G  = 4*SBUF*4;           // gemm4: 73728 B
    const int SMEM_QK = 2*128*68*4;         // qk:    69632 B
    const int SMEM_PV = (2*PVA + 2*PVB)*4;  // pv:    55296 B
    cudaFuncSetAttribute(gemm4_k<EPI_BIAS>, cudaFuncAttributeMaxDynamicSharedMemorySize, SMEM_G);
    cudaFuncSetAttribute(gemm4_k<EPI_RES>,  cudaFuncAttributeMaxDynamicSharedMemorySize, SMEM_G);
    cudaFuncSetAttribute(gemm4_k<EPI_GELU>, cudaFuncAttributeMaxDynamicSharedMemorySize, SMEM_G);
    cudaFuncSetAttribute(qk_k, cudaFuncAttributeMaxDynamicSharedMemorySize, SMEM_QK);
    cudaFuncSetAttribute(pv_k, cudaFuncAttributeMaxDynamicSharedMemorySize, SMEM_PV);

    {
        int total = T1_+T2_+T3_+T4_+T5_+T6_;
        prep_k<<<(total + 255)/256, 256>>>(wq, wk, wv, bq, bk, bv, wo, w1, w2,
                                           patch_w, qkvT, woT, w1T, w2T, patT, pb);
    }
    rnd_k<<<(B_*N_*256 + 255)/256, 256>>>(images, img, B_*N_*256);
    {
        dim3 g(D_/128, (B_*N_)/128);
        gemm4_k<EPI_BIAS><<<g, 128, SMEM_G>>>(img, patT, patch_b, nullptr, qkv,
                                              B_*N_, D_, 256);
    }
    assemble_k<<<(ROWS_*D_ + 255)/256, 256>>>(qkv, cls_tok, x);

    dim3 gq(QKV_N/128, ROWSP_/128);
    dim3 go(D_/128,    ROWSP_/128);
    dim3 g1(FF_/128,   ROWSP_/128);
    dim3 gqk(SP_/128, SP_/128, B_*H_);
    dim3 gpv(SP_/128, B_*H_);

    for (int l = 0; l < L_; l++) {
        ln_k<<<ROWS_/8, 256>>>(x, ln1_g + l*D_, ln1_b + l*D_, h);
        gemm4_k<EPI_BIAS><<<gq, 128, SMEM_G>>>(h, qkvT + (size_t)l*QKV_N*D_,
                                               pb + l*QKV_N, nullptr,
                                               qkv, ROWSP_, QKV_N, D_);
        qk_k<<<gqk, 128, SMEM_QK>>>(qkv, S);
        vt_k<<<(48*SEQ_*HD_ + 255)/256, 256>>>(qkv, vT);
        pv_k<<<gpv, 128, SMEM_PV>>>(S, vT, attn);
        gemm4_k<EPI_RES><<<go, 128, SMEM_G>>>(attn, woT + (size_t)l*D_*D_,
                                              bo + l*D_, x,
                                              x, ROWSP_, D_, D_);
        ln_k<<<ROWS_/8, 256>>>(x, ln2_g + l*D_, ln2_b + l*D_, h);
        gemm4_k<EPI_GELU><<<g1, 128, SMEM_G>>>(h, w1T + (size_t)l*FF_*D_,
                                               b1 + l*FF_, nullptr,
                                               mlp, ROWSP_, FF_, D_);
        gemm4_k<EPI_RES><<<go, 128, SMEM_G>>>(mlp, w2T + (size_t)l*D_*FF_,
                                              b2 + l*D_, x,
                                              x, ROWSP_, D_, FF_);
    }

    logits_k<<<(B_*N_*NC_ + 127)/128, 128>>>(x, cls_w, cls_b, lg);
    up_k<<<(B_*NC_*N_*256 + 255)/256, 256>>>(lg, dc_w, dc_b, out);
    (void)in_sizes; (void)n_in; (void)out_size;
}

// round 9
// speedup vs baseline: 3.6728x; 1.1583x over previous
#include <cuda_runtime.h>
#include <cuda_bf16.h>
#include <math.h>
#include <stdint.h>

// ---------------- problem constants ----------------
#define D_     384
#define H_     6
#define HD_    64
#define L_     4
#define B_     8
#define N_     1024
#define SEQ_   1025
#define ROWS_  (B_*SEQ_)     // 8200
#define ROWSP_ 8320          // padded: no M predicates in weight GEMMs
#define NC_    2
#define QKV_N  (3*D_)        // 1152
#define FF_    (4*D_)        // 1536
#define SP_    1152          // padded seq (9*128)

typedef unsigned long long u64;
typedef unsigned int u32;

__device__ __forceinline__ float f2tf32(float f) {
    u32 u; asm("cvt.rna.tf32.f32 %0, %1;" : "=r"(u) : "f"(f));
    return __uint_as_float(u);
}

#define MMA_TF32(c, a, b) \
    asm("mma.sync.aligned.m16n8k8.row.col.f32.tf32.tf32.f32 " \
        "{%0,%1,%2,%3}, {%4,%5,%6,%7}, {%8,%9}, {%0,%1,%2,%3};" \
        : "+f"(c[0]), "+f"(c[1]), "+f"(c[2]), "+f"(c[3]) \
        : "r"(a[0]), "r"(a[1]), "r"(a[2]), "r"(a[3]), "r"(b[0]), "r"(b[1]))

#define CP16(saddr, gptr) \
    asm volatile("cp.async.ca.shared.global [%0], [%1], 16;" :: "r"(saddr), "l"(gptr))
#define CP_COMMIT() asm volatile("cp.async.commit_group;" ::: "memory")
#define CP_WAIT0()  asm volatile("cp.async.wait_group 0;" ::: "memory")

__device__ __forceinline__ u32 smem_u32(const void* p) {
    u32 a;
    asm("{ .reg .u64 t; cvta.to.shared.u64 t, %1; cvt.u32.u64 %0, t; }" : "=r"(a) : "l"(p));
    return a;
}

// ---------------- scratch (device globals; no allocation allowed) ----------
__device__ float g_x[ROWSP_*D_];
__device__ float g_h[ROWSP_*D_];
__device__ float g_qkv[ROWSP_*QKV_N];
__device__ float g_attn[ROWSP_*D_];
__device__ float g_mlp[ROWSP_*FF_];
__device__ float g_pb[L_*QKV_N];
__device__ float g_qkvT[L_*QKV_N*D_];
__device__ float g_woT[L_*D_*D_];
__device__ float g_w1T[L_*FF_*D_];
__device__ float g_w2T[L_*D_*FF_];
__device__ float g_patT[D_*256];
__device__ float g_img[B_*N_*256];
__device__ float g_lg[B_*N_*NC_];

// ---------------- GEMM v4 (tf32 mma, 64x64 warp tiles, cp.async) -------------
#define EPI_BIAS 0
#define EPI_RES  1
#define EPI_GELU 2
#define EPI_RND  3
#define SSTRIDE 36
#define SBUF    (128*SSTRIDE)

__device__ __forceinline__ float gelu_f(float v) {
    return 0.5f * v * (1.f + erff(v * 0.70710678118654752f));
}

template<int EPI>
__global__ __launch_bounds__(128, 2)
void gemm4_k(const float* __restrict__ A, const float* __restrict__ Bm,
             const float* __restrict__ bias, const float* __restrict__ res,
             float* __restrict__ C, int M, int N, int K)
{
    extern __shared__ float sm[];
    const int tid  = threadIdx.x;
    const int lane = tid & 31, wid = tid >> 5;
    const int wm = (wid >> 1) * 64, wn = (wid & 1) * 64;
    const int g = lane >> 2, t = lane & 3;
    const size_t row0 = (size_t)blockIdx.y * 128;
    const size_t col0 = (size_t)blockIdx.x * 128;

    const int lr = tid >> 3;
    const int lk = (tid & 7) * 4;

    const float* Aptr = A + (row0 + lr) * K + lk;
    const float* Bptr = Bm + (col0 + lr) * K + lk;
    const u32 asb0 = smem_u32(sm);
    const u32 dst_off = (u32)(lr * SSTRIDE + lk) * 4;

    float c[4][8][4];
    #pragma unroll
    for (int i = 0; i < 4; i++)
        #pragma unroll
        for (int j = 0; j < 8; j++)
            #pragma unroll
            for (int f = 0; f < 4; f++) c[i][j][f] = 0.f;

    const int KT = K >> 5;

    {
        u32 ad = asb0 + dst_off;
        u32 bd = asb0 + 2*SBUF*4 + dst_off;
        #pragma unroll
        for (int it = 0; it < 8; it++) {
            CP16(ad + it*16*SSTRIDE*4, Aptr + (size_t)it*16*K);
            CP16(bd + it*16*SSTRIDE*4, Bptr + (size_t)it*16*K);
        }
        CP_COMMIT();
    }

    int buf = 0;
    for (int kt = 0; kt < KT; kt++) {
        CP_WAIT0();
        __syncthreads();
        if (kt + 1 < KT) {
            int k0 = (kt + 1) << 5;
            u32 ad = asb0 + (buf^1)*SBUF*4 + dst_off;
            u32 bd = asb0 + (2 + (buf^1))*SBUF*4 + dst_off;
            #pragma unroll
            for (int it = 0; it < 8; it++) {
                CP16(ad + it*16*SSTRIDE*4, Aptr + k0 + (size_t)it*16*K);
                CP16(bd + it*16*SSTRIDE*4, Bptr + k0 + (size_t)it*16*K);
            }
            CP_COMMIT();
        }
        const float* As_ = sm + buf*SBUF;
        const float* Bs_ = sm + (2 + buf)*SBUF;
        #pragma unroll
        for (int ks = 0; ks < 4; ks++) {
            const int k8 = ks * 8;
            u32 a[4][4], b[8][2];
            #pragma unroll
            for (int i = 0; i < 4; i++) {
                int m0 = wm + 16*i;
                a[i][0] = __float_as_uint(As_[(m0+g  )*SSTRIDE + k8 + t  ]);
                a[i][1] = __float_as_uint(As_[(m0+g+8)*SSTRIDE + k8 + t  ]);
                a[i][2] = __float_as_uint(As_[(m0+g  )*SSTRIDE + k8 + t+4]);
                a[i][3] = __float_as_uint(As_[(m0+g+8)*SSTRIDE + k8 + t+4]);
            }
            #pragma unroll
            for (int j = 0; j < 8; j++) {
                int n0 = wn + 8*j;
                b[j][0] = __float_as_uint(Bs_[(n0+g)*SSTRIDE + k8 + t  ]);
                b[j][1] = __float_as_uint(Bs_[(n0+g)*SSTRIDE + k8 + t+4]);
            }
            #pragma unroll
            for (int i = 0; i < 4; i++)
                #pragma unroll
                for (int j = 0; j < 8; j++)
                    MMA_TF32(c[i][j], a[i], b[j]);
        }
        __syncthreads();
        buf ^= 1;
    }

    #pragma unroll
    for (int i = 0; i < 4; i++) {
        size_t r0 = row0 + wm + 16*i + g;
        size_t r1 = r0 + 8;
        #pragma unroll
        for (int j = 0; j < 8; j++) {
            int cb = (int)col0 + wn + 8*j + 2*t;
            float b0 = bias[cb], b1 = bias[cb+1];
            float v0 = c[i][j][0] + b0, v1 = c[i][j][1] + b1;
            float v2 = c[i][j][2] + b0, v3 = c[i][j][3] + b1;
            if (EPI == EPI_RES) {
                float2 ra = *(const float2*)&res[r0*N + cb];
                float2 rb = *(const float2*)&res[r1*N + cb];
                v0 += ra.x; v1 += ra.y; v2 += rb.x; v3 += rb.y;
            }
            if (EPI == EPI_GELU) {
                v0 = f2tf32(gelu_f(v0)); v1 = f2tf32(gelu_f(v1));
                v2 = f2tf32(gelu_f(v2)); v3 = f2tf32(gelu_f(v3));
            }
            if (EPI == EPI_RND) {
                v0 = f2tf32(v0); v1 = f2tf32(v1);
                v2 = f2tf32(v2); v3 = f2tf32(v3);
            }
            *(float2*)&C[r0*N + cb] = make_float2(v0, v1);
            *(float2*)&C[r1*N + cb] = make_float2(v2, v3);
        }
    }
}

// ---------------- fused flash attention --------------------------------------
// Grid (9, 48), 256 threads. Warp (wr=wid>>1 in 0..3, wc=wid&1):
// S tile per warp = 32 q-rows x 64 k-cols; O partial 32x64 in regs.
// smem: Qs[128][68] | Ks0 | Ks1 | Vs0 | Vs1 (each 128x68). 174080 B.
#define FS_STRIDE 68
#define FS_TILE   (128*FS_STRIDE)     // 8704 floats

__global__ __launch_bounds__(256, 1)
void flash_k(const float* __restrict__ qkv, float* __restrict__ attn)
{
    extern __shared__ float sm[];
    __shared__ float rsx[4][32];
    const int tid  = threadIdx.x;
    const int lane = tid & 31, wid = tid >> 5;
    const int wr = wid >> 1, wc = wid & 1;
    const int wm = wr*32, wn = wc*64;
    const int g = lane >> 2, t = lane & 3;
    const int q0 = blockIdx.x * 128;
    const int bh = blockIdx.y, b = bh / H_, h = bh % H_;
    const float* Qb = qkv + (size_t)b*SEQ_*QKV_N + h*HD_;
    const float* Kb = Qb + D_;
    const float* Vb = Qb + 2*D_;

    const int lr = tid >> 3;          // 0..31
    const int kc = (tid & 7) * 8;     // 0..56
    const u32 sb = smem_u32(sm);

    // ---- Q tile (pre-scaled by 1/8; qkv already tf32-rounded) ----
    #pragma unroll
    for (int it = 0; it < 4; it++) {
        int r = lr + 32*it;
        int q = min(q0 + r, SEQ_-1);
        const float4* qa = (const float4*)(Qb + (size_t)q*QKV_N + kc);
        float4 a0 = qa[0], a1 = qa[1];
        a0.x *= 0.125f; a0.y *= 0.125f; a0.z *= 0.125f; a0.w *= 0.125f;
        a1.x *= 0.125f; a1.y *= 0.125f; a1.z *= 0.125f; a1.w *= 0.125f;
        *(float4*)(sm + r*FS_STRIDE + kc)     = a0;
        *(float4*)(sm + r*FS_STRIDE + kc + 4) = a1;
    }

    // ---- prefetch K/V tile 0 ----
    {
        #pragma unroll
        for (int it = 0; it < 4; it++) {
            int r = lr + 32*it;
            int j = min(r, SEQ_-1);
            u32 doff = (u32)(r*FS_STRIDE + kc)*4;
            CP16(sb + (FS_TILE          )*4 + doff,      Kb + (size_t)j*QKV_N + kc);
            CP16(sb + (FS_TILE          )*4 + doff + 16, Kb + (size_t)j*QKV_N + kc + 4);
            CP16(sb + (FS_TILE*3        )*4 + doff,      Vb + (size_t)j*QKV_N + kc);
            CP16(sb + (FS_TILE*3        )*4 + doff + 16, Vb + (size_t)j*QKV_N + kc + 4);
        }
        CP_COMMIT();
    }

    float c2[2][8][4];
    #pragma unroll
    for (int i = 0; i < 2; i++)
        #pragma unroll
        for (int j = 0; j < 8; j++)
            #pragma unroll
            for (int f = 0; f < 4; f++) c2[i][j][f] = 0.f;
    float rs[2][2] = {{0.f,0.f},{0.f,0.f}};

    int buf = 0;
    for (int kb = 0; kb < 9; kb++) {
        CP_WAIT0();
        __syncthreads();
        if (kb + 1 < 9) {
            int nb = buf ^ 1;
            #pragma unroll
            for (int it = 0; it < 4; it++) {
                int r = lr + 32*it;
                int j = min((kb+1)*128 + r, SEQ_-1);
                u32 doff = (u32)(r*FS_STRIDE + kc)*4;
                CP16(sb + (FS_TILE*(1+nb))*4 + doff,      Kb + (size_t)j*QKV_N + kc);
                CP16(sb + (FS_TILE*(1+nb))*4 + doff + 16, Kb + (size_t)j*QKV_N + kc + 4);
                CP16(sb + (FS_TILE*(3+nb))*4 + doff,      Vb + (size_t)j*QKV_N + kc);
                CP16(sb + (FS_TILE*(3+nb))*4 + doff + 16, Vb + (size_t)j*QKV_N + kc + 4);
            }
            CP_COMMIT();
        }

        const float* Ksb = sm + FS_TILE*(1+buf);
        const float* Vsb = sm + FS_TILE*(3+buf);

        // ---- S = (Q/8) @ K^T for this tile ----
        float c[2][8][4];
        #pragma unroll
        for (int i = 0; i < 2; i++)
            #pragma unroll
            for (int j = 0; j < 8; j++)
                #pragma unroll
                for (int f = 0; f < 4; f++) c[i][j][f] = 0.f;

        #pragma unroll
        for (int ks = 0; ks < 8; ks++) {
            const int k8 = ks*8;
            u32 a[2][4], bb[8][2];
            #pragma unroll
            for (int i = 0; i < 2; i++) {
                int m0 = wm + 16*i;
                a[i][0] = __float_as_uint(sm[(m0+g  )*FS_STRIDE + k8 + t  ]);
                a[i][1] = __float_as_uint(sm[(m0+g+8)*FS_STRIDE + k8 + t  ]);
                a[i][2] = __float_as_uint(sm[(m0+g  )*FS_STRIDE + k8 + t+4]);
                a[i][3] = __float_as_uint(sm[(m0+g+8)*FS_STRIDE + k8 + t+4]);
            }
            #pragma unroll
            for (int j = 0; j < 8; j++) {
                int n0 = wn + 8*j;
                bb[j][0] = __float_as_uint(Ksb[(n0+g)*FS_STRIDE + k8 + t  ]);
                bb[j][1] = __float_as_uint(Ksb[(n0+g)*FS_STRIDE + k8 + t+4]);
            }
            #pragma unroll
            for (int i = 0; i < 2; i++)
                #pragma unroll
                for (int j = 0; j < 8; j++)
                    MMA_TF32(c[i][j], a[i], bb[j]);
        }

        // ---- P = exp(S), mask pads, tf32-round, accumulate row sums ----
        #pragma unroll
        for (int i = 0; i < 2; i++) {
            #pragma unroll
            for (int j = 0; j < 8; j++) {
                int colb = kb*128 + wn + 8*j + 2*t;
                float p0 = (colb   < SEQ_) ? f2tf32(__expf(c[i][j][0])) : 0.f;
                float p1 = (colb+1 < SEQ_) ? f2tf32(__expf(c[i][j][1])) : 0.f;
                float p2 = (colb   < SEQ_) ? f2tf32(__expf(c[i][j][2])) : 0.f;
                float p3 = (colb+1 < SEQ_) ? f2tf32(__expf(c[i][j][3])) : 0.f;
                c[i][j][0] = p0; c[i][j][1] = p1; c[i][j][2] = p2; c[i][j][3] = p3;
                rs[i][0] += p0 + p1;
                rs[i][1] += p2 + p3;
            }
        }

        // ---- O += P @ V (A fragments from P via shfl) ----
        const int sL = (lane & ~3) | (t >> 1);
        const int sH = sL | 2;
        const bool odd = (t & 1);
        #pragma unroll
        for (int ks = 0; ks < 8; ks++) {
            u32 a2[2][4];
            #pragma unroll
            for (int i = 0; i < 2; i++) {
                float p0 = __shfl_sync(0xffffffffu, c[i][ks][0], sL);
                float p1 = __shfl_sync(0xffffffffu, c[i][ks][1], sL);
                float p2 = __shfl_sync(0xffffffffu, c[i][ks][2], sL);
                float p3 = __shfl_sync(0xffffffffu, c[i][ks][3], sL);
                float q0 = __shfl_sync(0xffffffffu, c[i][ks][0], sH);
                float q1 = __shfl_sync(0xffffffffu, c[i][ks][1], sH);
                float q2 = __shfl_sync(0xffffffffu, c[i][ks][2], sH);
                float q3 = __shfl_sync(0xffffffffu, c[i][ks][3], sH);
                a2[i][0] = __float_as_uint(odd ? p1 : p0);
                a2[i][1] = __float_as_uint(odd ? p3 : p2);
                a2[i][2] = __float_as_uint(odd ? q1 : q0);
                a2[i][3] = __float_as_uint(odd ? q3 : q2);
            }
            #pragma unroll
            for (int j = 0; j < 8; j++) {
                u32 bb[2];
                bb[0] = __float_as_uint(Vsb[(wn + ks*8 + t    )*FS_STRIDE + 8*j + g]);
                bb[1] = __float_as_uint(Vsb[(wn + ks*8 + t + 4)*FS_STRIDE + 8*j + g]);
                #pragma unroll
                for (int i = 0; i < 2; i++)
                    MMA_TF32(c2[i][j], a2[i], bb);
            }
        }
        buf ^= 1;
    }

    // ---- reduce row sums across quad (t lanes) ----
    #pragma unroll
    for (int i = 0; i < 2; i++) {
        #pragma unroll
        for (int s = 0; s < 2; s++) {
            float v = rs[i][s];
            v += __shfl_xor_sync(0xffffffffu, v, 1);
            v += __shfl_xor_sync(0xffffffffu, v, 2);
            rs[i][s] = v;
        }
    }

    // ---- cross-warp-pair reduction through smem (reuse Q region) ----
    __syncthreads();
    if (wc == 1) {
        float* Ox = sm + wr*(32*FS_STRIDE);
        #pragma unroll
        for (int i = 0; i < 2; i++) {
            #pragma unroll
            for (int j = 0; j < 8; j++) {
                *(float2*)(Ox + (16*i+g  )*FS_STRIDE + 8*j + 2*t) = make_float2(c2[i][j][0], c2[i][j][1]);
                *(float2*)(Ox + (16*i+g+8)*FS_STRIDE + 8*j + 2*t) = make_float2(c2[i][j][2], c2[i][j][3]);
            }
        }
        if (t == 0) {
            rsx[wr][16*0+g]   = rs[0][0];
            rsx[wr][16*0+g+8] = rs[0][1];
            rsx[wr][16*1+g]   = rs[1][0];
            rsx[wr][16*1+g+8] = rs[1][1];
        }
    }
    __syncthreads();
    if (wc == 0) {
        const float* Ox = sm + wr*(32*FS_STRIDE);
        #pragma unroll
        for (int i = 0; i < 2; i++) {
            int r0 = q0 + wm + 16*i + g;
            int r1 = r0 + 8;
            float inv0 = 1.f / (rs[i][0] + rsx[wr][16*i+g]);
            float inv1 = 1.f / (rs[i][1] + rsx[wr][16*i+g+8]);
            #pragma unroll
            for (int j = 0; j < 8; j++) {
                float2 e0 = *(const float2*)(Ox + (16*i+g  )*FS_STRIDE + 8*j + 2*t);
                float2 e1 = *(const float2*)(Ox + (16*i+g+8)*FS_STRIDE + 8*j + 2*t);
                if (r0 < SEQ_) {
                    size_t o = ((size_t)b*SEQ_ + r0)*D_ + h*HD_ + 8*j + 2*t;
                    *(float2*)&attn[o] = make_float2(f2tf32((c2[i][j][0]+e0.x)*inv0),
                                                     f2tf32((c2[i][j][1]+e0.y)*inv0));
                }
                if (r1 < SEQ_) {
                    size_t o = ((size_t)b*SEQ_ + r1)*D_ + h*HD_ + 8*j + 2*t;
                    *(float2*)&attn[o] = make_float2(f2tf32((c2[i][j][2]+e1.x)*inv1),
                                                     f2tf32((c2[i][j][3]+e1.y)*inv1));
                }
            }
        }
    }
}

// ---------------- layernorm: warp per row, shfl reductions -------------------
__global__ __launch_bounds__(256)
void ln_k(const float* __restrict__ x, const float* __restrict__ g,
          const float* __restrict__ b, float* __restrict__ y)
{
    const int w    = threadIdx.x >> 5;
    const int lane = threadIdx.x & 31;
    const int row  = blockIdx.x * 8 + w;
    const float* xr = x + (size_t)row*D_;
    float v[12];
    float s = 0.f;
    #pragma unroll
    for (int i = 0; i < 12; i++) { v[i] = xr[lane + 32*i]; s += v[i]; }
    #pragma unroll
    for (int o = 16; o > 0; o >>= 1) s += __shfl_xor_sync(0xffffffffu, s, o);
    float mu = s * (1.f/D_);
    float s2 = 0.f;
    #pragma unroll
    for (int i = 0; i < 12; i++) { float d = v[i]-mu; s2 += d*d; }
    #pragma unroll
    for (int o = 16; o > 0; o >>= 1) s2 += __shfl_xor_sync(0xffffffffu, s2, o);
    float inv = rsqrtf(s2*(1.f/D_) + 1e-5f);
    float* yr = y + (size_t)row*D_;
    #pragma unroll
    for (int i = 0; i < 12; i++) {
        int c = lane + 32*i;
        yr[c] = f2tf32((v[i]-mu)*inv*g[c] + b[c]);
    }
}

// ---------------- patch-embed assemble ---------------------------------------
__global__ void assemble_k(const float* __restrict__ tmp, const float* __restrict__ cls,
                           float* __restrict__ x)
{
    int idx = blockIdx.x*blockDim.x + threadIdx.x;
    if (idx >= ROWS_*D_) return;
    int d = idx % D_;
    int rp = idx / D_;
    int pos = rp % SEQ_;
    int b = rp / SEQ_;
    float val = (pos == 0) ? cls[d] : tmp[((size_t)b*N_ + pos-1)*D_ + d];
    float expo = (float)(d & ~1) * (1.f/(float)D_);
    float ang = (float)pos / powf(10000.f, expo);
    float pe = (d & 1) ? cosf(ang) : sinf(ang);
    x[idx] = val + pe;
}

// ---------------- all weight prep in ONE kernel ------------------------------
#define T1_ (L_*QKV_N*D_)
#define T2_ (L_*D_*D_)
#define T3_ (L_*FF_*D_)
#define T4_ (L_*D_*FF_)
#define T5_ (D_*256)
#define T6_ (L_*QKV_N)
__global__ void prep_k(const float* __restrict__ wq, const float* __restrict__ wk,
                       const float* __restrict__ wv, const float* __restrict__ bq,
                       const float* __restrict__ bk, const float* __restrict__ bv,
                       const float* __restrict__ wo, const float* __restrict__ w1,
                       const float* __restrict__ w2, const float* __restrict__ pat,
                       float* __restrict__ qkvT, float* __restrict__ woT,
                       float* __restrict__ w1T, float* __restrict__ w2T,
                       float* __restrict__ patT, float* __restrict__ pb)
{
    int idx = blockIdx.x*blockDim.x + threadIdx.x;
    if (idx < T1_) {
        int k = idx % D_; int r = idx / D_; int n = r % QKV_N; int l = r / QKV_N;
        int sec = n / D_, jj = n % D_, h = jj >> 6, e = jj & 63;
        const float* w = (sec == 0) ? wq : (sec == 1) ? wk : wv;
        qkvT[idx] = f2tf32(w[(((size_t)l*H_ + h)*D_ + k)*HD_ + e]);
    } else if (idx < T1_+T2_) {
        int i = idx - T1_;
        int k = i % D_; int r = i / D_; int n = r % D_; int l = r / D_;
        woT[i] = f2tf32(wo[((size_t)l*D_ + k)*D_ + n]);
    } else if (idx < T1_+T2_+T3_) {
        int i = idx - (T1_+T2_);
        int k = i % D_; int r = i / D_; int n = r % FF_; int l = r / FF_;
        w1T[i] = f2tf32(w1[((size_t)l*D_ + k)*FF_ + n]);
    } else if (idx < T1_+T2_+T3_+T4_) {
        int i = idx - (T1_+T2_+T3_);
        int k = i % FF_; int r = i / FF_; int n = r % D_; int l = r / D_;
        w2T[i] = f2tf32(w2[((size_t)l*FF_ + k)*D_ + n]);
    } else if (idx < T1_+T2_+T3_+T4_+T5_) {
        int i = idx - (T1_+T2_+T3_+T4_);
        int k = i % 256; int n = i / 256;
        patT[i] = f2tf32(pat[(size_t)k*D_ + n]);
    } else if (idx < T1_+T2_+T3_+T4_+T5_+T6_) {
        int i = idx - (T1_+T2_+T3_+T4_+T5_);
        int n = i % QKV_N; int l = i / QKV_N;
        int sec = n / D_, jj = n % D_, h = jj >> 6, e = jj & 63;
        const float* bb = (sec == 0) ? bq : (sec == 1) ? bk : bv;
        pb[i] = bb[((size_t)l*H_ + h)*HD_ + e];
    }
}

// ---------------- plain tf32 round -------------------------------------------
__global__ void rnd_k(const float* __restrict__ src, float* __restrict__ dst, int total)
{
    int idx = blockIdx.x*blockDim.x + threadIdx.x;
    if (idx >= total) return;
    dst[idx] = f2tf32(src[idx]);
}

// ---------------- classifier logits (NC=2) -----------------------------------
__global__ void logits_k(const float* __restrict__ x, const float* __restrict__ cw,
                         const float* __restrict__ cb, float* __restrict__ lg)
{
    int idx = blockIdx.x*blockDim.x + threadIdx.x;
    if (idx >= B_*N_*NC_) return;
    int c = idx & 1;
    int bn = idx >> 1;
    int n = bn % N_, b = bn / N_;
    const float4* xr = (const float4*)(x + ((size_t)b*SEQ_ + n + 1)*D_);
    float s = cb[c];
    #pragma unroll 4
    for (int d4 = 0; d4 < D_/4; d4++) {
        float4 xv = xr[d4];
        s += xv.x*cw[(d4*4+0)*NC_ + c] + xv.y*cw[(d4*4+1)*NC_ + c]
           + xv.z*cw[(d4*4+2)*NC_ + c] + xv.w*cw[(d4*4+3)*NC_ + c];
    }
    lg[idx] = s;
}

// ---------------- deconv upsample ---------------------------------------------
__global__ void up_k(const float* __restrict__ lg, const float* __restrict__ dw,
                     const float* __restrict__ db, float* __restrict__ out)
{
    int idx = blockIdx.x*blockDim.x + threadIdx.x;
    if (idx >= B_*NC_*N_*16*16) return;
    int ww = idx & 15;
    int t = idx >> 4;
    int hh = t & 15; t >>= 4;
    int n = t % N_;  t /= N_;
    int o = t & 1;   int b = t >> 1;
    float s = db[o];
    #pragma unroll
    for (int c = 0; c < NC_; c++)
        s += lg[((size_t)b*N_ + n)*NC_ + c] * dw[((c*NC_ + o)*16 + hh)*16 + ww];
    out[idx] = s;
}

// ---------------- launch ------------------------------------------------------
extern "C" void kernel_launch(void* const* d_in, const int* in_sizes, int n_in,
                              void* d_out, int out_size)
{
    const float* images  = (const float*)d_in[0];
    const float* patch_w = (const float*)d_in[2];
    const float* patch_b = (const float*)d_in[3];
    const float* cls_tok = (const float*)d_in[4];
    const float* ln1_g   = (const float*)d_in[5];
    const float* ln1_b   = (const float*)d_in[6];
    const float* wq      = (const float*)d_in[7];
    const float* bq      = (const float*)d_in[8];
    const float* wk      = (const float*)d_in[9];
    const float* bk      = (const float*)d_in[10];
    const float* wv      = (const float*)d_in[11];
    const float* bv      = (const float*)d_in[12];
    const float* wo      = (const float*)d_in[13];
    const float* bo      = (const float*)d_in[14];
    const float* ln2_g   = (const float*)d_in[15];
    const float* ln2_b   = (const float*)d_in[16];
    const float* w1      = (const float*)d_in[17];
    const float* b1      = (const float*)d_in[18];
    const float* w2      = (const float*)d_in[19];
    const float* b2      = (const float*)d_in[20];
    const float* cls_w   = (const float*)d_in[21];
    const float* cls_b   = (const float*)d_in[22];
    const float* dc_w    = (const float*)d_in[23];
    const float* dc_b    = (const float*)d_in[24];
    float* out = (float*)d_out;

    float *x, *h, *qkv, *attn, *mlp, *pb, *lg;
    float *qkvT, *woT, *w1T, *w2T, *patT, *img;
    cudaGetSymbolAddress((void**)&x,    g_x);
    cudaGetSymbolAddress((void**)&h,    g_h);
    cudaGetSymbolAddress((void**)&qkv,  g_qkv);
    cudaGetSymbolAddress((void**)&attn, g_attn);
    cudaGetSymbolAddress((void**)&mlp,  g_mlp);
    cudaGetSymbolAddress((void**)&pb,   g_pb);
    cudaGetSymbolAddress((void**)&qkvT, g_qkvT);
    cudaGetSymbolAddress((void**)&woT,  g_woT);
    cudaGetSymbolAddress((void**)&w1T,  g_w1T);
    cudaGetSymbolAddress((void**)&w2T,  g_w2T);
    cudaGetSymbolAddress((void**)&patT, g_patT);
    cudaGetSymbolAddress((void**)&img,  g_img);
    cudaGetSymbolAddress((void**)&lg,   g_lg);

    const int SMEM_G = 4*SBUF*4;            // gemm4: 73728 B
    const int SMEM_F = 5*FS_TILE*4;         // flash: 174080 B
    cudaFuncSetAttribute(gemm4_k<EPI_BIAS>, cudaFuncAttributeMaxDynamicSharedMemorySize, SMEM_G);
    cudaFuncSetAttribute(gemm4_k<EPI_RES>,  cudaFuncAttributeMaxDynamicSharedMemorySize, SMEM_G);
    cudaFuncSetAttribute(gemm4_k<EPI_GELU>, cudaFuncAttributeMaxDynamicSharedMemorySize, SMEM_G);
    cudaFuncSetAttribute(gemm4_k<EPI_RND>,  cudaFuncAttributeMaxDynamicSharedMemorySize, SMEM_G);
    cudaFuncSetAttribute(flash_k, cudaFuncAttributeMaxDynamicSharedMemorySize, SMEM_F);

    {
        int total = T1_+T2_+T3_+T4_+T5_+T6_;
        prep_k<<<(total + 255)/256, 256>>>(wq, wk, wv, bq, bk, bv, wo, w1, w2,
                                           patch_w, qkvT, woT, w1T, w2T, patT, pb);
    }
    rnd_k<<<(B_*N_*256 + 255)/256, 256>>>(images, img, B_*N_*256);
    {
        dim3 g(D_/128, (B_*N_)/128);
        gemm4_k<EPI_BIAS><<<g, 128, SMEM_G>>>(img, patT, patch_b, nullptr, qkv,
                                              B_*N_, D_, 256);
    }
    assemble_k<<<(ROWS_*D_ + 255)/256, 256>>>(qkv, cls_tok, x);

    dim3 gq(QKV_N/128, ROWSP_/128);
    dim3 go(D_/128,    ROWSP_/128);
    dim3 g1(FF_/128,   ROWSP_/128);
    dim3 gf(SP_/128, B_*H_);

    for (int l = 0; l < L_; l++) {
        ln_k<<<ROWS_/8, 256>>>(x, ln1_g + l*D_, ln1_b + l*D_, h);
        gemm4_k<EPI_RND><<<gq, 128, SMEM_G>>>(h, qkvT + (size_t)l*QKV_N*D_,
                                              pb + l*QKV_N, nullptr,
                                              qkv, ROWSP_, QKV_N, D_);
        flash_k<<<gf, 256, SMEM_F>>>(qkv, attn);
        gemm4_k<EPI_RES><<<go, 128, SMEM_G>>>(attn, woT + (size_t)l*D_*D_,
                                              bo + l*D_, x,
                                              x, ROWSP_, D_, D_);
        ln_k<<<ROWS_/8, 256>>>(x, ln2_g + l*D_, ln2_b + l*D_, h);
        gemm4_k<EPI_GELU><<<g1, 128, SMEM_G>>>(h, w1T + (size_t)l*FF_*D_,
                                               b1 + l*FF_, nullptr,
                                               mlp, ROWSP_, FF_, D_);
        gemm4_k<EPI_RES><<<go, 128, SMEM_G>>>(mlp, w2T + (size_t)l*D_*FF_,
                                              b2 + l*D_, x,
                                              x, ROWSP_, D_, FF_);
    }

    logits_k<<<(B_*N_*NC_ + 127)/128, 128>>>(x, cls_w, cls_b, lg);
    up_k<<<(B_*NC_*N_*256 + 255)/256, 256>>>(lg, dc_w, dc_b, out);
    (void)in_sizes; (void)n_in; (void)out_size;
}